// round 1
// baseline (speedup 1.0000x reference)
#include <cuda_runtime.h>
#include <cstdint>
#include <cstddef>

#define B_ 4
#define S_ 2048
#define D_ 1024
#define H_ 16
#define DK_ 64
#define DFF_ 4096
#define EPS_ 1e-6f
#define NTOK (B_ * S_)          // 8192
#define NBH  (B_ * H_)          // 64

// ---------------- scratch (device globals; no runtime allocation) ----------------
__device__ float g_xn[(size_t)NTOK * D_];                     // layernorm output (reused for ln1 and ln2)
__device__ float g_q[(size_t)NTOK * D_];
__device__ float g_k[(size_t)NTOK * D_];
__device__ float g_v[(size_t)NTOK * D_];
__device__ float g_attn[(size_t)NTOK * D_];
__device__ float g_x1[(size_t)NTOK * D_];
__device__ float g_scores[(size_t)NBH * S_ * S_];             // 1.07 GB
__device__ float g_h[(size_t)NTOK * DFF_];

// ---------------- LayerNorm: one block per token row (D=1024) ----------------
__global__ __launch_bounds__(256) void ln_kernel(
    const float* __restrict__ x, const float* __restrict__ w,
    const float* __restrict__ b, float* __restrict__ y)
{
    __shared__ float red[256];
    const int row = blockIdx.x;
    const int tid = threadIdx.x;
    const float* xr = x + (size_t)row * D_;
    float v0 = xr[tid], v1 = xr[tid + 256], v2 = xr[tid + 512], v3 = xr[tid + 768];

    float s = v0 + v1 + v2 + v3;
    red[tid] = s; __syncthreads();
    for (int off = 128; off > 0; off >>= 1) {
        if (tid < off) red[tid] += red[tid + off];
        __syncthreads();
    }
    float mean = red[0] * (1.0f / D_);
    __syncthreads();

    float d0 = v0 - mean, d1 = v1 - mean, d2 = v2 - mean, d3 = v3 - mean;
    float sq = d0 * d0 + d1 * d1 + d2 * d2 + d3 * d3;
    red[tid] = sq; __syncthreads();
    for (int off = 128; off > 0; off >>= 1) {
        if (tid < off) red[tid] += red[tid + off];
        __syncthreads();
    }
    // ddof=1 (unbiased), divide by (std + eps)   — matches reference exactly
    float std1 = sqrtf(red[0] / (float)(D_ - 1));
    float rinv = 1.0f / (std1 + EPS_);

    float* yr = y + (size_t)row * D_;
    yr[tid]       = w[tid]       * d0 * rinv + b[tid];
    yr[tid + 256] = w[tid + 256] * d1 * rinv + b[tid + 256];
    yr[tid + 512] = w[tid + 512] * d2 * rinv + b[tid + 512];
    yr[tid + 768] = w[tid + 768] * d3 * rinv + b[tid + 768];
}

// ---------------- SGEMM: C[M,N] = A[M,K] @ B[K,N] (+bias)(+relu)(+residual) ----------------
// 128x128x16 tile, 256 threads, 8x8 microtile. All dims divisible (M=8192, N/K in {1024,4096}).
template<bool RELU, bool HAS_RES>
__global__ __launch_bounds__(256) void sgemm_kernel(
    const float* __restrict__ A, const float* __restrict__ Bm,
    const float* __restrict__ bias, const float* __restrict__ res,
    float* __restrict__ C, int M, int N, int K)
{
    __shared__ float As[16][128];
    __shared__ float Bs[16][128];

    const int tid = threadIdx.x;
    const int tm = tid / 16, tn = tid % 16;
    const int rowBase = blockIdx.y * 128;
    const int colBase = blockIdx.x * 128;

    const float* Ablk = A + (size_t)rowBase * K;
    const float* Bblk = Bm + colBase;

    float acc[8][8];
    #pragma unroll
    for (int i = 0; i < 8; i++)
        #pragma unroll
        for (int j = 0; j < 8; j++) acc[i][j] = 0.f;

    for (int k0 = 0; k0 < K; k0 += 16) {
        // A tile: 128 rows x 16 cols = 512 float4
        #pragma unroll
        for (int it = 0; it < 2; it++) {
            int idx = tid + it * 256;
            int r = idx >> 2, c4 = idx & 3;
            float4 v = *(const float4*)(Ablk + (size_t)r * K + k0 + c4 * 4);
            As[c4 * 4 + 0][r] = v.x;
            As[c4 * 4 + 1][r] = v.y;
            As[c4 * 4 + 2][r] = v.z;
            As[c4 * 4 + 3][r] = v.w;
        }
        // B tile: 16 rows x 128 cols = 512 float4
        #pragma unroll
        for (int it = 0; it < 2; it++) {
            int idx = tid + it * 256;
            int r = idx >> 5, c4 = idx & 31;
            float4 v = *(const float4*)(Bblk + (size_t)(k0 + r) * N + c4 * 4);
            *(float4*)&Bs[r][c4 * 4] = v;
        }
        __syncthreads();

        #pragma unroll
        for (int kk = 0; kk < 16; kk++) {
            float a[8], b[8];
            #pragma unroll
            for (int i = 0; i < 8; i++) a[i] = As[kk][tm * 8 + i];
            #pragma unroll
            for (int j = 0; j < 8; j++) b[j] = Bs[kk][tn * 8 + j];
            #pragma unroll
            for (int i = 0; i < 8; i++)
                #pragma unroll
                for (int j = 0; j < 8; j++)
                    acc[i][j] = fmaf(a[i], b[j], acc[i][j]);
        }
        __syncthreads();
    }

    #pragma unroll
    for (int i = 0; i < 8; i++) {
        int row = rowBase + tm * 8 + i;
        #pragma unroll
        for (int j = 0; j < 8; j++) {
            int col = colBase + tn * 8 + j;
            float v = acc[i][j] + bias[col];
            if (RELU) v = fmaxf(v, 0.f);
            if (HAS_RES) v += res[(size_t)row * N + col];
            C[(size_t)row * N + col] = v;
        }
    }
}

// ---------------- scores = Q·K^T / 8, masked  (per b,h) ----------------
// grid: (S/64 key tiles, S/64 query tiles, B*H). 64x64 output, 256 threads, 4x4 microtile.
__global__ __launch_bounds__(256) void qk_kernel(
    const float* __restrict__ q, const float* __restrict__ k,
    const int* __restrict__ mask, float* __restrict__ scores)
{
    __shared__ float Qs[64][64];
    __shared__ float Ks[64][64];
    const int bh = blockIdx.z;
    const int b = bh / H_, h = bh % H_;
    const int tid = threadIdx.x;
    const int tm = tid / 16, tn = tid % 16;
    const int qBase = blockIdx.y * 64;
    const int kBase = blockIdx.x * 64;

    // load Q and K tiles (64 rows x 64 dk), stored transposed [dk][row]
    #pragma unroll
    for (int it = 0; it < 4; it++) {
        int idx = tid + it * 256;                 // 0..1023
        int r = idx >> 4, c4 = idx & 15;
        float4 vq = *(const float4*)(q + (size_t)(b * S_ + qBase + r) * D_ + h * DK_ + c4 * 4);
        Qs[c4 * 4 + 0][r] = vq.x; Qs[c4 * 4 + 1][r] = vq.y;
        Qs[c4 * 4 + 2][r] = vq.z; Qs[c4 * 4 + 3][r] = vq.w;
        float4 vk = *(const float4*)(k + (size_t)(b * S_ + kBase + r) * D_ + h * DK_ + c4 * 4);
        Ks[c4 * 4 + 0][r] = vk.x; Ks[c4 * 4 + 1][r] = vk.y;
        Ks[c4 * 4 + 2][r] = vk.z; Ks[c4 * 4 + 3][r] = vk.w;
    }
    __syncthreads();

    float acc[4][4];
    #pragma unroll
    for (int i = 0; i < 4; i++)
        #pragma unroll
        for (int j = 0; j < 4; j++) acc[i][j] = 0.f;

    #pragma unroll 8
    for (int kk = 0; kk < 64; kk++) {
        float a[4], bb[4];
        #pragma unroll
        for (int i = 0; i < 4; i++) a[i] = Qs[kk][tm * 4 + i];
        #pragma unroll
        for (int j = 0; j < 4; j++) bb[j] = Ks[kk][tn * 4 + j];
        #pragma unroll
        for (int i = 0; i < 4; i++)
            #pragma unroll
            for (int j = 0; j < 4; j++)
                acc[i][j] = fmaf(a[i], bb[j], acc[i][j]);
    }

    const float scale = 0.125f;   // 1/sqrt(64)
    #pragma unroll
    for (int i = 0; i < 4; i++) {
        int qi = qBase + tm * 4 + i;
        #pragma unroll
        for (int j = 0; j < 4; j++) {
            int kj = kBase + tn * 4 + j;
            float v = acc[i][j] * scale;
            if (mask[b * S_ + kj] == 0) v = -1e30f;
            scores[((size_t)bh * S_ + qi) * S_ + kj] = v;
        }
    }
}

// ---------------- row softmax over scores (row length S=2048) ----------------
__global__ __launch_bounds__(256) void softmax_kernel(float* __restrict__ scores)
{
    __shared__ float red[256];
    float* p = scores + (size_t)blockIdx.x * S_;
    const int tid = threadIdx.x;

    float m = -3.4e38f;
    float v[8];
    #pragma unroll
    for (int i = 0; i < 8; i++) { v[i] = p[tid + i * 256]; m = fmaxf(m, v[i]); }
    red[tid] = m; __syncthreads();
    for (int off = 128; off > 0; off >>= 1) {
        if (tid < off) red[tid] = fmaxf(red[tid], red[tid + off]);
        __syncthreads();
    }
    m = red[0]; __syncthreads();

    float s = 0.f;
    #pragma unroll
    for (int i = 0; i < 8; i++) { v[i] = __expf(v[i] - m); s += v[i]; }
    red[tid] = s; __syncthreads();
    for (int off = 128; off > 0; off >>= 1) {
        if (tid < off) red[tid] += red[tid + off];
        __syncthreads();
    }
    float inv = 1.0f / red[0];
    #pragma unroll
    for (int i = 0; i < 8; i++) p[tid + i * 256] = v[i] * inv;
}

// ---------------- out = P @ V  (per b,h: [S,S]@[S,64]) ----------------
// grid: (1, S/64, B*H). 64x64 output tile (N=DK=64), BK=32, 256 threads, 4x4 microtile.
__global__ __launch_bounds__(256) void pv_kernel(
    const float* __restrict__ scores, const float* __restrict__ v,
    float* __restrict__ attn)
{
    __shared__ float Ps[32][64];
    __shared__ float Vs[32][64];
    const int bh = blockIdx.z;
    const int b = bh / H_, h = bh % H_;
    const int tid = threadIdx.x;
    const int tm = tid / 16, tn = tid % 16;
    const int qBase = blockIdx.y * 64;

    float acc[4][4];
    #pragma unroll
    for (int i = 0; i < 4; i++)
        #pragma unroll
        for (int j = 0; j < 4; j++) acc[i][j] = 0.f;

    for (int k0 = 0; k0 < S_; k0 += 32) {
        // P tile: 64 rows x 32 k = 512 float4, store transposed
        #pragma unroll
        for (int it = 0; it < 2; it++) {
            int idx = tid + it * 256;
            int r = idx >> 3, c4 = idx & 7;
            float4 pv = *(const float4*)(scores + ((size_t)bh * S_ + qBase + r) * S_ + k0 + c4 * 4);
            Ps[c4 * 4 + 0][r] = pv.x; Ps[c4 * 4 + 1][r] = pv.y;
            Ps[c4 * 4 + 2][r] = pv.z; Ps[c4 * 4 + 3][r] = pv.w;
        }
        // V tile: 32 k-rows x 64 dk
        #pragma unroll
        for (int it = 0; it < 2; it++) {
            int idx = tid + it * 256;
            int r = idx >> 4, c4 = idx & 15;
            float4 vv = *(const float4*)(v + (size_t)(b * S_ + k0 + r) * D_ + h * DK_ + c4 * 4);
            *(float4*)&Vs[r][c4 * 4] = vv;
        }
        __syncthreads();

        #pragma unroll
        for (int kk = 0; kk < 32; kk++) {
            float a[4], bb[4];
            #pragma unroll
            for (int i = 0; i < 4; i++) a[i] = Ps[kk][tm * 4 + i];
            #pragma unroll
            for (int j = 0; j < 4; j++) bb[j] = Vs[kk][tn * 4 + j];
            #pragma unroll
            for (int i = 0; i < 4; i++)
                #pragma unroll
                for (int j = 0; j < 4; j++)
                    acc[i][j] = fmaf(a[i], bb[j], acc[i][j]);
        }
        __syncthreads();
    }

    #pragma unroll
    for (int i = 0; i < 4; i++) {
        int qi = qBase + tm * 4 + i;
        #pragma unroll
        for (int j = 0; j < 4; j++) {
            int dj = tn * 4 + j;
            attn[(size_t)(b * S_ + qi) * D_ + h * DK_ + dj] = acc[i][j];
        }
    }
}

// ---------------- host launcher ----------------
extern "C" void kernel_launch(void* const* d_in, const int* in_sizes, int n_in,
                              void* d_out, int out_size)
{
    const float* x     = (const float*)d_in[0];
    const int*   mask  = (const int*)  d_in[1];
    const float* wq    = (const float*)d_in[2];
    const float* bq    = (const float*)d_in[3];
    const float* wk    = (const float*)d_in[4];
    const float* bk    = (const float*)d_in[5];
    const float* wv    = (const float*)d_in[6];
    const float* bv    = (const float*)d_in[7];
    const float* wo    = (const float*)d_in[8];
    const float* bo    = (const float*)d_in[9];
    const float* w1    = (const float*)d_in[10];
    const float* b1    = (const float*)d_in[11];
    const float* w2    = (const float*)d_in[12];
    const float* b2    = (const float*)d_in[13];
    const float* ln1w  = (const float*)d_in[14];
    const float* ln1b  = (const float*)d_in[15];
    const float* ln2w  = (const float*)d_in[16];
    const float* ln2b  = (const float*)d_in[17];
    float* out = (float*)d_out;

    float *xn, *q, *k, *v, *attn, *x1, *scores, *hbuf;
    cudaGetSymbolAddress((void**)&xn,     g_xn);
    cudaGetSymbolAddress((void**)&q,      g_q);
    cudaGetSymbolAddress((void**)&k,      g_k);
    cudaGetSymbolAddress((void**)&v,      g_v);
    cudaGetSymbolAddress((void**)&attn,   g_attn);
    cudaGetSymbolAddress((void**)&x1,     g_x1);
    cudaGetSymbolAddress((void**)&scores, g_scores);
    cudaGetSymbolAddress((void**)&hbuf,   g_h);

    // 1) LN1
    ln_kernel<<<NTOK, 256>>>(x, ln1w, ln1b, xn);

    // 2) Q, K, V projections: [8192,1024] @ [1024,1024]
    dim3 gProj(D_ / 128, NTOK / 128);
    sgemm_kernel<false, false><<<gProj, 256>>>(xn, wq, bq, nullptr, q, NTOK, D_, D_);
    sgemm_kernel<false, false><<<gProj, 256>>>(xn, wk, bk, nullptr, k, NTOK, D_, D_);
    sgemm_kernel<false, false><<<gProj, 256>>>(xn, wv, bv, nullptr, v, NTOK, D_, D_);

    // 3) scores = QK^T/8 masked
    dim3 gQK(S_ / 64, S_ / 64, NBH);
    qk_kernel<<<gQK, 256>>>(q, k, mask, scores);

    // 4) softmax rows
    softmax_kernel<<<NBH * S_, 256>>>(scores);

    // 5) attn = P @ V
    dim3 gPV(1, S_ / 64, NBH);
    pv_kernel<<<gPV, 256>>>(scores, v, attn);

    // 6) x1 = x + attn @ wo + bo
    sgemm_kernel<false, true><<<gProj, 256>>>(attn, wo, bo, x, x1, NTOK, D_, D_);

    // 7) LN2
    ln_kernel<<<NTOK, 256>>>(x1, ln2w, ln2b, xn);

    // 8) h = relu(xn @ w1 + b1)   [8192,1024]x[1024,4096]
    dim3 gF1(DFF_ / 128, NTOK / 128);
    sgemm_kernel<true, false><<<gF1, 256>>>(xn, w1, b1, nullptr, hbuf, NTOK, DFF_, D_);

    // 9) out = x1 + h @ w2 + b2   [8192,4096]x[4096,1024]
    sgemm_kernel<false, true><<<gProj, 256>>>(hbuf, w2, b2, x1, out, NTOK, D_, DFF_);
}

// round 4
// speedup vs baseline: 2.9494x; 2.9494x over previous
#include <cuda_runtime.h>
#include <cstdint>
#include <cstddef>

#define B_ 4
#define S_ 2048
#define D_ 1024
#define H_ 16
#define DK_ 64
#define DFF_ 4096
#define EPS_ 1e-6f
#define NTOK (B_ * S_)          // 8192
#define NBH  (B_ * H_)          // 64
#define RS 36                   // smem row stride in floats (32 + 4 pad)

// ================= scratch (device globals; no runtime allocation) =================
__device__ float g_xn[(size_t)NTOK * D_];
__device__ float g_q[(size_t)NTOK * D_];
__device__ float g_k[(size_t)NTOK * D_];
__device__ float g_v[(size_t)NTOK * D_];
__device__ float g_vT[(size_t)NBH * DK_ * S_];
__device__ float g_attn[(size_t)NTOK * D_];
__device__ float g_x1[(size_t)NTOK * D_];
__device__ float g_scores[(size_t)NBH * S_ * S_];
__device__ float g_h[(size_t)NTOK * DFF_];
// transposed (tf32-rounded) weights: [N, K] K-major
__device__ float g_wqT[(size_t)D_ * D_];
__device__ float g_wkT[(size_t)D_ * D_];
__device__ float g_wvT[(size_t)D_ * D_];
__device__ float g_woT[(size_t)D_ * D_];
__device__ float g_w1T[(size_t)DFF_ * D_];
__device__ float g_w2T[(size_t)D_ * DFF_];

// ================= helpers =================
__device__ __forceinline__ uint32_t smem_u32(const void* p) {
    uint32_t a;
    asm("{ .reg .u64 t; cvta.to.shared.u64 t, %1; cvt.u32.u64 %0, t; }" : "=r"(a) : "l"(p));
    return a;
}
__device__ __forceinline__ float to_tf32(float x) {
    uint32_t u;
    asm("cvt.rna.tf32.f32 %0, %1;" : "=r"(u) : "f"(x));
    return __uint_as_float(u);
}
__device__ __forceinline__ void cp_async16(uint32_t smem, const void* g) {
    asm volatile("cp.async.cg.shared.global [%0], [%1], 16;" :: "r"(smem), "l"(g));
}
__device__ __forceinline__ void cp_commit() { asm volatile("cp.async.commit_group;" ::: "memory"); }
template <int N>
__device__ __forceinline__ void cp_wait() { asm volatile("cp.async.wait_group %0;" :: "n"(N) : "memory"); }

// m16n8k8 tf32 mma: d += a @ b   (a row-major 16x8, b col-major 8x8, fp32 accum)
__device__ __forceinline__ void mma_m16n8k8(float d[4], const uint32_t a[4], const uint32_t b[2]) {
    asm volatile(
        "mma.sync.aligned.m16n8k8.row.col.f32.tf32.tf32.f32 "
        "{%0,%1,%2,%3}, {%4,%5,%6,%7}, {%8,%9}, {%0,%1,%2,%3};"
        : "+f"(d[0]), "+f"(d[1]), "+f"(d[2]), "+f"(d[3])
        : "r"(a[0]), "r"(a[1]), "r"(a[2]), "r"(a[3]), "r"(b[0]), "r"(b[1]));
}

// ================= unified tf32 mma GEMM =================
// C[M,N] = A[M,K] @ Bt[N,K]^T, tiles BM=128 x BN, BK=32, 256 threads (8 warps).
// MODE 0: dense. MODE 1: batched QK^T (z = b*H + h; scale+mask epilogue).
// MODE 2: batched PV (z = bh; A=scores, Bt=vT per head, C=attn slice).
#define MD_DENSE 0
#define MD_QK 1
#define MD_PV 2

template<int BN, int MODE, bool HAS_BIAS, bool RELU, bool HAS_RES, bool ROUND>
__global__ __launch_bounds__(256, 1) void mma_gemm(
    const float* __restrict__ A0, const float* __restrict__ B0,
    const float* __restrict__ bias, const float* __restrict__ res,
    float* __restrict__ C0, const int* __restrict__ mask,
    int M, int N, int K, int lda, int ldb, int ldc)
{
    constexpr int BM = 128;
    constexpr int BK = 32;
    constexpr int NT = BN / 16;            // n8 tiles per warp
    constexpr int SF = (BM + BN) * RS;     // floats per stage
    extern __shared__ float smem[];

    const int tid = threadIdx.x, lane = tid & 31, wid = tid >> 5;
    const int wrow = (wid & 3) * 32;           // warp row base within tile
    const int wcol = (wid >> 2) * (BN / 2);    // warp col base within tile
    const int rowBase = blockIdx.y * BM;
    const int colBase = blockIdx.x * BN;
    const int z = blockIdx.z;

    int bIdx = 0;
    const float* A = A0;
    const float* Bt = B0;
    float* C = C0;
    if (MODE == MD_QK) {
        bIdx = z / H_;
        const int h = z % H_;
        A  = A0 + (size_t)bIdx * S_ * D_ + h * DK_;
        Bt = B0 + (size_t)bIdx * S_ * D_ + h * DK_;
        C  = C0 + (size_t)z * S_ * S_;
    } else if (MODE == MD_PV) {
        const int b2 = z / H_;
        const int h = z % H_;
        A  = A0 + (size_t)z * S_ * S_;
        Bt = B0 + (size_t)z * DK_ * S_;
        C  = C0 + (size_t)b2 * S_ * D_ + h * DK_;
    }

    const uint32_t sbase = smem_u32(smem);

    auto load_chunk = [&](int c) {
        const int s = c & 1;
        const uint32_t as = sbase + (uint32_t)(s * SF) * 4u;
        const uint32_t bs = as + (uint32_t)(BM * RS) * 4u;
        const int kOff = c * BK;
        #pragma unroll
        for (int i = 0; i < 4; i++) {                   // A tile: 128x32 = 1024 float4
            int idx = tid + i * 256;
            int r = idx >> 3, q4 = idx & 7;
            cp_async16(as + (uint32_t)(r * RS + q4 * 4) * 4u,
                       A + (size_t)(rowBase + r) * lda + kOff + q4 * 4);
        }
        #pragma unroll
        for (int i = 0; i < BN / 32; i++) {             // B tile: BNx32
            int idx = tid + i * 256;
            int r = idx >> 3, q4 = idx & 7;
            cp_async16(bs + (uint32_t)(r * RS + q4 * 4) * 4u,
                       Bt + (size_t)(colBase + r) * ldb + kOff + q4 * 4);
        }
    };

    float acc[2][NT][4];
    #pragma unroll
    for (int mt = 0; mt < 2; mt++)
        #pragma unroll
        for (int nt = 0; nt < NT; nt++)
            #pragma unroll
            for (int i = 0; i < 4; i++) acc[mt][nt][i] = 0.f;

    const int NC = K / BK;
    load_chunk(0); cp_commit();

    for (int c = 0; c < NC; c++) {
        if (c + 1 < NC) load_chunk(c + 1);
        cp_commit();
        cp_wait<1>();
        __syncthreads();
        const float* As = smem + (c & 1) * SF;
        const float* Bs = As + BM * RS;

        #pragma unroll
        for (int ks = 0; ks < 4; ks++) {
            uint32_t afr[2][4];
            #pragma unroll
            for (int mt = 0; mt < 2; mt++) {
                const int r = wrow + mt * 16 + (lane >> 2);
                const int cc = ks * 8 + (lane & 3);
                afr[mt][0] = __float_as_uint(As[r * RS + cc]);
                afr[mt][1] = __float_as_uint(As[(r + 8) * RS + cc]);
                afr[mt][2] = __float_as_uint(As[r * RS + cc + 4]);
                afr[mt][3] = __float_as_uint(As[(r + 8) * RS + cc + 4]);
            }
            #pragma unroll
            for (int nt = 0; nt < NT; nt++) {
                const int n = wcol + nt * 8 + (lane >> 2);
                const int kk = ks * 8 + (lane & 3);
                uint32_t bfr[2];
                bfr[0] = __float_as_uint(Bs[n * RS + kk]);
                bfr[1] = __float_as_uint(Bs[n * RS + kk + 4]);
                mma_m16n8k8(acc[0][nt], afr[0], bfr);
                mma_m16n8k8(acc[1][nt], afr[1], bfr);
            }
        }
        __syncthreads();
    }

    // ---- epilogue: direct float2 stores ----
    #pragma unroll
    for (int mt = 0; mt < 2; mt++) {
        const int r0 = rowBase + wrow + mt * 16 + (lane >> 2);
        #pragma unroll
        for (int nt = 0; nt < NT; nt++) {
            const int col = colBase + wcol + nt * 8 + 2 * (lane & 3);
            float vx0 = acc[mt][nt][0], vy0 = acc[mt][nt][1];   // row r0
            float vx1 = acc[mt][nt][2], vy1 = acc[mt][nt][3];   // row r0+8
            if (MODE == MD_QK) {
                vx0 *= 0.125f; vy0 *= 0.125f; vx1 *= 0.125f; vy1 *= 0.125f;
                const int m0 = mask[bIdx * S_ + col];
                const int m1 = mask[bIdx * S_ + col + 1];
                if (m0 == 0) { vx0 = -1e30f; vx1 = -1e30f; }
                if (m1 == 0) { vy0 = -1e30f; vy1 = -1e30f; }
            }
            if (HAS_BIAS) {
                const float b0v = bias[col], b1v = bias[col + 1];
                vx0 += b0v; vy0 += b1v; vx1 += b0v; vy1 += b1v;
            }
            if (RELU) {
                vx0 = fmaxf(vx0, 0.f); vy0 = fmaxf(vy0, 0.f);
                vx1 = fmaxf(vx1, 0.f); vy1 = fmaxf(vy1, 0.f);
            }
            if (HAS_RES) {
                vx0 += res[(size_t)r0 * ldc + col];
                vy0 += res[(size_t)r0 * ldc + col + 1];
                vx1 += res[(size_t)(r0 + 8) * ldc + col];
                vy1 += res[(size_t)(r0 + 8) * ldc + col + 1];
            }
            if (ROUND) {
                vx0 = to_tf32(vx0); vy0 = to_tf32(vy0);
                vx1 = to_tf32(vx1); vy1 = to_tf32(vy1);
            }
            float2 p0 = make_float2(vx0, vy0);
            float2 p1 = make_float2(vx1, vy1);
            *(float2*)(C + (size_t)r0 * ldc + col) = p0;
            *(float2*)(C + (size_t)(r0 + 8) * ldc + col) = p1;
        }
    }
}

// ================= weight transpose + tf32 round: W[K,N] -> Wt[N,K] =================
__global__ __launch_bounds__(256) void transpose_tf32_kernel(
    const float* __restrict__ W, float* __restrict__ Wt, int Kd, int Nd)
{
    __shared__ float t[32][33];
    const int k0 = blockIdx.y * 32, n0 = blockIdx.x * 32;
    const int tx = threadIdx.x & 31, ty = threadIdx.x >> 5;
    #pragma unroll
    for (int i = 0; i < 32; i += 8)
        t[ty + i][tx] = W[(size_t)(k0 + ty + i) * Nd + n0 + tx];
    __syncthreads();
    #pragma unroll
    for (int i = 0; i < 32; i += 8)
        Wt[(size_t)(n0 + ty + i) * Kd + k0 + tx] = to_tf32(t[tx][ty + i]);
}

// ================= V transpose per head: v -> vT[bh][dk][s] (tf32-rounded) =================
__global__ __launch_bounds__(256) void vtrans_kernel(
    const float* __restrict__ v, float* __restrict__ vT)
{
    __shared__ float t[32][33];
    const int z = blockIdx.z;
    const int b = z / H_, h = z % H_;
    const int s0 = blockIdx.x * 32, d0 = blockIdx.y * 32;
    const int tx = threadIdx.x & 31, ty = threadIdx.x >> 5;
    #pragma unroll
    for (int i = 0; i < 32; i += 8)
        t[ty + i][tx] = v[(size_t)(b * S_ + s0 + ty + i) * D_ + h * DK_ + d0 + tx];
    __syncthreads();
    #pragma unroll
    for (int i = 0; i < 32; i += 8)
        vT[((size_t)z * DK_ + d0 + ty + i) * S_ + s0 + tx] = to_tf32(t[tx][ty + i]);
}

// ================= LayerNorm (ddof=1, /(std+eps)), tf32-rounded output =================
template<bool ROUND>
__global__ __launch_bounds__(256) void ln_kernel(
    const float* __restrict__ x, const float* __restrict__ w,
    const float* __restrict__ b, float* __restrict__ y)
{
    __shared__ float red[256];
    const int row = blockIdx.x;
    const int tid = threadIdx.x;
    const float* xr = x + (size_t)row * D_;
    float v0 = xr[tid], v1 = xr[tid + 256], v2 = xr[tid + 512], v3 = xr[tid + 768];

    red[tid] = v0 + v1 + v2 + v3; __syncthreads();
    for (int off = 128; off > 0; off >>= 1) {
        if (tid < off) red[tid] += red[tid + off];
        __syncthreads();
    }
    float mean = red[0] * (1.0f / D_);
    __syncthreads();

    float d0 = v0 - mean, d1 = v1 - mean, d2 = v2 - mean, d3 = v3 - mean;
    red[tid] = d0 * d0 + d1 * d1 + d2 * d2 + d3 * d3; __syncthreads();
    for (int off = 128; off > 0; off >>= 1) {
        if (tid < off) red[tid] += red[tid + off];
        __syncthreads();
    }
    float std1 = sqrtf(red[0] / (float)(D_ - 1));
    float rinv = 1.0f / (std1 + EPS_);

    float* yr = y + (size_t)row * D_;
    float o0 = w[tid] * d0 * rinv + b[tid];
    float o1 = w[tid + 256] * d1 * rinv + b[tid + 256];
    float o2 = w[tid + 512] * d2 * rinv + b[tid + 512];
    float o3 = w[tid + 768] * d3 * rinv + b[tid + 768];
    if (ROUND) { o0 = to_tf32(o0); o1 = to_tf32(o1); o2 = to_tf32(o2); o3 = to_tf32(o3); }
    yr[tid] = o0; yr[tid + 256] = o1; yr[tid + 512] = o2; yr[tid + 768] = o3;
}

// ================= row softmax (tf32-rounded output, feeds PV mma) =================
__global__ __launch_bounds__(256) void softmax_kernel(float* __restrict__ scores)
{
    __shared__ float red[256];
    float* p = scores + (size_t)blockIdx.x * S_;
    const int tid = threadIdx.x;

    float m = -3.4e38f;
    float v[8];
    #pragma unroll
    for (int i = 0; i < 8; i++) { v[i] = p[tid + i * 256]; m = fmaxf(m, v[i]); }
    red[tid] = m; __syncthreads();
    for (int off = 128; off > 0; off >>= 1) {
        if (tid < off) red[tid] = fmaxf(red[tid], red[tid + off]);
        __syncthreads();
    }
    m = red[0]; __syncthreads();

    float s = 0.f;
    #pragma unroll
    for (int i = 0; i < 8; i++) { v[i] = __expf(v[i] - m); s += v[i]; }
    red[tid] = s; __syncthreads();
    for (int off = 128; off > 0; off >>= 1) {
        if (tid < off) red[tid] += red[tid + off];
        __syncthreads();
    }
    float inv = 1.0f / red[0];
    #pragma unroll
    for (int i = 0; i < 8; i++) p[tid + i * 256] = to_tf32(v[i] * inv);
}

// ================= host launcher =================
extern "C" void kernel_launch(void* const* d_in, const int* in_sizes, int n_in,
                              void* d_out, int out_size)
{
    const float* x    = (const float*)d_in[0];
    const int*   mask = (const int*)  d_in[1];
    const float* wq   = (const float*)d_in[2];
    const float* bq   = (const float*)d_in[3];
    const float* wk   = (const float*)d_in[4];
    const float* bk   = (const float*)d_in[5];
    const float* wv   = (const float*)d_in[6];
    const float* bv   = (const float*)d_in[7];
    const float* wo   = (const float*)d_in[8];
    const float* bo   = (const float*)d_in[9];
    const float* w1   = (const float*)d_in[10];
    const float* b1   = (const float*)d_in[11];
    const float* w2   = (const float*)d_in[12];
    const float* b2   = (const float*)d_in[13];
    const float* ln1w = (const float*)d_in[14];
    const float* ln1b = (const float*)d_in[15];
    const float* ln2w = (const float*)d_in[16];
    const float* ln2b = (const float*)d_in[17];
    float* out = (float*)d_out;

    float *xn, *q, *k, *v, *vT, *attn, *x1, *scores, *hbuf;
    float *wqT, *wkT, *wvT, *woT, *w1T, *w2T;
    cudaGetSymbolAddress((void**)&xn,     g_xn);
    cudaGetSymbolAddress((void**)&q,      g_q);
    cudaGetSymbolAddress((void**)&k,      g_k);
    cudaGetSymbolAddress((void**)&v,      g_v);
    cudaGetSymbolAddress((void**)&vT,     g_vT);
    cudaGetSymbolAddress((void**)&attn,   g_attn);
    cudaGetSymbolAddress((void**)&x1,     g_x1);
    cudaGetSymbolAddress((void**)&scores, g_scores);
    cudaGetSymbolAddress((void**)&hbuf,   g_h);
    cudaGetSymbolAddress((void**)&wqT,    g_wqT);
    cudaGetSymbolAddress((void**)&wkT,    g_wkT);
    cudaGetSymbolAddress((void**)&wvT,    g_wvT);
    cudaGetSymbolAddress((void**)&woT,    g_woT);
    cudaGetSymbolAddress((void**)&w1T,    g_w1T);
    cudaGetSymbolAddress((void**)&w2T,    g_w2T);

    // kernel instantiations + dynamic smem opt-in
    auto kQKV  = mma_gemm<128, MD_DENSE, true,  false, false, true>;   // bias, round
    auto kRES  = mma_gemm<128, MD_DENSE, true,  false, true,  false>;  // bias + residual
    auto kFFN1 = mma_gemm<128, MD_DENSE, true,  true,  false, true>;   // bias + relu + round
    auto kQK   = mma_gemm<128, MD_QK,    false, false, false, false>;
    auto kPV   = mma_gemm<64,  MD_PV,    false, false, false, true>;

    const int SM128 = 2 * (128 + 128) * RS * 4;   // 73728
    const int SM64  = 2 * (128 + 64)  * RS * 4;   // 55296
    cudaFuncSetAttribute(kQKV,  cudaFuncAttributeMaxDynamicSharedMemorySize, SM128);
    cudaFuncSetAttribute(kRES,  cudaFuncAttributeMaxDynamicSharedMemorySize, SM128);
    cudaFuncSetAttribute(kFFN1, cudaFuncAttributeMaxDynamicSharedMemorySize, SM128);
    cudaFuncSetAttribute(kQK,   cudaFuncAttributeMaxDynamicSharedMemorySize, SM128);
    cudaFuncSetAttribute(kPV,   cudaFuncAttributeMaxDynamicSharedMemorySize, SM64);

    // weight transposes (+ tf32 rounding)
    {
        dim3 gT(D_ / 32, D_ / 32);
        transpose_tf32_kernel<<<gT, 256>>>(wq, wqT, D_, D_);
        transpose_tf32_kernel<<<gT, 256>>>(wk, wkT, D_, D_);
        transpose_tf32_kernel<<<gT, 256>>>(wv, wvT, D_, D_);
        transpose_tf32_kernel<<<gT, 256>>>(wo, woT, D_, D_);
        dim3 gT1(DFF_ / 32, D_ / 32);
        transpose_tf32_kernel<<<gT1, 256>>>(w1, w1T, D_, DFF_);
        dim3 gT2(D_ / 32, DFF_ / 32);
        transpose_tf32_kernel<<<gT2, 256>>>(w2, w2T, DFF_, D_);
    }

    // 1) LN1 (tf32-rounded)
    ln_kernel<true><<<NTOK, 256>>>(x, ln1w, ln1b, xn);

    // 2) QKV projections
    dim3 gProj(D_ / 128, NTOK / 128, 1);
    kQKV<<<gProj, 256, SM128>>>(xn, wqT, bq, nullptr, q, nullptr, NTOK, D_, D_, D_, D_, D_);
    kQKV<<<gProj, 256, SM128>>>(xn, wkT, bk, nullptr, k, nullptr, NTOK, D_, D_, D_, D_, D_);
    kQKV<<<gProj, 256, SM128>>>(xn, wvT, bv, nullptr, v, nullptr, NTOK, D_, D_, D_, D_, D_);

    // 3) scores = QK^T/8 (masked)
    dim3 gQK(S_ / 128, S_ / 128, NBH);
    kQK<<<gQK, 256, SM128>>>(q, k, nullptr, nullptr, scores, mask, S_, S_, DK_, D_, D_, S_);

    // 4) softmax (tf32-rounded)
    softmax_kernel<<<NBH * S_, 256>>>(scores);

    // 5) vT = v^T per head (tf32-rounded)
    dim3 gVT(S_ / 32, DK_ / 32, NBH);
    vtrans_kernel<<<gVT, 256>>>(v, vT);

    // 6) attn = P @ V (tf32-rounded)
    dim3 gPV(1, S_ / 128, NBH);
    kPV<<<gPV, 256, SM64>>>(scores, vT, nullptr, nullptr, attn, nullptr, S_, DK_, S_, S_, S_, D_);

    // 7) x1 = x + attn @ wo + bo
    kRES<<<gProj, 256, SM128>>>(attn, woT, bo, x, x1, nullptr, NTOK, D_, D_, D_, D_, D_);

    // 8) LN2 (tf32-rounded)
    ln_kernel<true><<<NTOK, 256>>>(x1, ln2w, ln2b, xn);

    // 9) h = relu(xn @ w1 + b1) (tf32-rounded)
    dim3 gF1(DFF_ / 128, NTOK / 128, 1);
    kFFN1<<<gF1, 256, SM128>>>(xn, w1T, b1, nullptr, hbuf, nullptr, NTOK, DFF_, D_, D_, D_, DFF_);

    // 10) out = x1 + h @ w2 + b2
    kRES<<<gProj, 256, SM128>>>(hbuf, w2T, b2, x1, out, nullptr, NTOK, D_, DFF_, DFF_, DFF_, D_);
}

// round 5
// speedup vs baseline: 3.6465x; 1.2364x over previous
#include <cuda_runtime.h>
#include <cstdint>
#include <cstddef>

#define B_ 4
#define S_ 2048
#define D_ 1024
#define H_ 16
#define DK_ 64
#define DFF_ 4096
#define EPS_ 1e-6f
#define NTOK (B_ * S_)          // 8192
#define NBH  (B_ * H_)          // 64
#define RS 36                   // gemm smem row stride in floats (32 + 4 pad)

// ================= scratch (device globals; no runtime allocation) =================
__device__ float g_xn[(size_t)NTOK * D_];
__device__ float g_q[(size_t)NTOK * D_];
__device__ float g_k[(size_t)NTOK * D_];
__device__ float g_v[(size_t)NTOK * D_];
__device__ float g_attn[(size_t)NTOK * D_];
__device__ float g_x1[(size_t)NTOK * D_];
__device__ float g_h[(size_t)NTOK * DFF_];
// transposed (tf32-rounded) weights: [N, K] K-major
__device__ float g_wqT[(size_t)D_ * D_];
__device__ float g_wkT[(size_t)D_ * D_];
__device__ float g_wvT[(size_t)D_ * D_];
__device__ float g_woT[(size_t)D_ * D_];
__device__ float g_w1T[(size_t)DFF_ * D_];
__device__ float g_w2T[(size_t)D_ * DFF_];

// ================= helpers =================
__device__ __forceinline__ uint32_t smem_u32(const void* p) {
    uint32_t a;
    asm("{ .reg .u64 t; cvta.to.shared.u64 t, %1; cvt.u32.u64 %0, t; }" : "=r"(a) : "l"(p));
    return a;
}
__device__ __forceinline__ float to_tf32(float x) {
    uint32_t u;
    asm("cvt.rna.tf32.f32 %0, %1;" : "=r"(u) : "f"(x));
    return __uint_as_float(u);
}
__device__ __forceinline__ void cp_async16(uint32_t smem, const void* g) {
    asm volatile("cp.async.cg.shared.global [%0], [%1], 16;" :: "r"(smem), "l"(g));
}
__device__ __forceinline__ void cp_commit() { asm volatile("cp.async.commit_group;" ::: "memory"); }
template <int N>
__device__ __forceinline__ void cp_wait() { asm volatile("cp.async.wait_group %0;" :: "n"(N) : "memory"); }

// m16n8k8 tf32 mma: d += a @ b
__device__ __forceinline__ void mma_m16n8k8(float d[4], const uint32_t a[4], const uint32_t b[2]) {
    asm volatile(
        "mma.sync.aligned.m16n8k8.row.col.f32.tf32.tf32.f32 "
        "{%0,%1,%2,%3}, {%4,%5,%6,%7}, {%8,%9}, {%0,%1,%2,%3};"
        : "+f"(d[0]), "+f"(d[1]), "+f"(d[2]), "+f"(d[3])
        : "r"(a[0]), "r"(a[1]), "r"(a[2]), "r"(a[3]), "r"(b[0]), "r"(b[1]));
}

// ================= dense tf32 mma GEMM: C[M,N] = A[M,K] @ Bt[N,K]^T =================
template<bool HAS_BIAS, bool RELU, bool HAS_RES, bool ROUND>
__global__ __launch_bounds__(256, 1) void mma_gemm(
    const float* __restrict__ A, const float* __restrict__ Bt,
    const float* __restrict__ bias, const float* __restrict__ res,
    float* __restrict__ C, int M, int N, int K, int lda, int ldb, int ldc)
{
    constexpr int BM = 128;
    constexpr int BN = 128;
    constexpr int BK = 32;
    constexpr int NT = BN / 16;
    constexpr int SF = (BM + BN) * RS;
    extern __shared__ float smem[];

    const int tid = threadIdx.x, lane = tid & 31, wid = tid >> 5;
    const int wrow = (wid & 3) * 32;
    const int wcol = (wid >> 2) * (BN / 2);
    const int rowBase = blockIdx.y * BM;
    const int colBase = blockIdx.x * BN;

    const uint32_t sbase = smem_u32(smem);

    auto load_chunk = [&](int c) {
        const int s = c & 1;
        const uint32_t as = sbase + (uint32_t)(s * SF) * 4u;
        const uint32_t bs = as + (uint32_t)(BM * RS) * 4u;
        const int kOff = c * BK;
        #pragma unroll
        for (int i = 0; i < 4; i++) {
            int idx = tid + i * 256;
            int r = idx >> 3, q4 = idx & 7;
            cp_async16(as + (uint32_t)(r * RS + q4 * 4) * 4u,
                       A + (size_t)(rowBase + r) * lda + kOff + q4 * 4);
        }
        #pragma unroll
        for (int i = 0; i < 4; i++) {
            int idx = tid + i * 256;
            int r = idx >> 3, q4 = idx & 7;
            cp_async16(bs + (uint32_t)(r * RS + q4 * 4) * 4u,
                       Bt + (size_t)(colBase + r) * ldb + kOff + q4 * 4);
        }
    };

    float acc[2][NT][4];
    #pragma unroll
    for (int mt = 0; mt < 2; mt++)
        #pragma unroll
        for (int nt = 0; nt < NT; nt++)
            #pragma unroll
            for (int i = 0; i < 4; i++) acc[mt][nt][i] = 0.f;

    const int NC = K / BK;
    load_chunk(0); cp_commit();

    for (int c = 0; c < NC; c++) {
        if (c + 1 < NC) load_chunk(c + 1);
        cp_commit();
        cp_wait<1>();
        __syncthreads();
        const float* As = smem + (c & 1) * SF;
        const float* Bs = As + BM * RS;

        #pragma unroll
        for (int ks = 0; ks < 4; ks++) {
            uint32_t afr[2][4];
            #pragma unroll
            for (int mt = 0; mt < 2; mt++) {
                const int r = wrow + mt * 16 + (lane >> 2);
                const int cc = ks * 8 + (lane & 3);
                afr[mt][0] = __float_as_uint(As[r * RS + cc]);
                afr[mt][1] = __float_as_uint(As[(r + 8) * RS + cc]);
                afr[mt][2] = __float_as_uint(As[r * RS + cc + 4]);
                afr[mt][3] = __float_as_uint(As[(r + 8) * RS + cc + 4]);
            }
            #pragma unroll
            for (int nt = 0; nt < NT; nt++) {
                const int n = wcol + nt * 8 + (lane >> 2);
                const int kk = ks * 8 + (lane & 3);
                uint32_t bfr[2];
                bfr[0] = __float_as_uint(Bs[n * RS + kk]);
                bfr[1] = __float_as_uint(Bs[n * RS + kk + 4]);
                mma_m16n8k8(acc[0][nt], afr[0], bfr);
                mma_m16n8k8(acc[1][nt], afr[1], bfr);
            }
        }
        __syncthreads();
    }

    #pragma unroll
    for (int mt = 0; mt < 2; mt++) {
        const int r0 = rowBase + wrow + mt * 16 + (lane >> 2);
        #pragma unroll
        for (int nt = 0; nt < NT; nt++) {
            const int col = colBase + wcol + nt * 8 + 2 * (lane & 3);
            float vx0 = acc[mt][nt][0], vy0 = acc[mt][nt][1];
            float vx1 = acc[mt][nt][2], vy1 = acc[mt][nt][3];
            if (HAS_BIAS) {
                const float b0v = bias[col], b1v = bias[col + 1];
                vx0 += b0v; vy0 += b1v; vx1 += b0v; vy1 += b1v;
            }
            if (RELU) {
                vx0 = fmaxf(vx0, 0.f); vy0 = fmaxf(vy0, 0.f);
                vx1 = fmaxf(vx1, 0.f); vy1 = fmaxf(vy1, 0.f);
            }
            if (HAS_RES) {
                vx0 += res[(size_t)r0 * ldc + col];
                vy0 += res[(size_t)r0 * ldc + col + 1];
                vx1 += res[(size_t)(r0 + 8) * ldc + col];
                vy1 += res[(size_t)(r0 + 8) * ldc + col + 1];
            }
            if (ROUND) {
                vx0 = to_tf32(vx0); vy0 = to_tf32(vy0);
                vx1 = to_tf32(vx1); vy1 = to_tf32(vy1);
            }
            *(float2*)(C + (size_t)r0 * ldc + col) = make_float2(vx0, vy0);
            *(float2*)(C + (size_t)(r0 + 8) * ldc + col) = make_float2(vx1, vy1);
        }
    }
}

// ================= flash attention (tf32 mma, online softmax) =================
// grid: (S/128 q-tiles, B*H). 256 threads, warp w owns q rows [16w, 16w+16).
#define FA_BKV 64
#define QS_ST 68
#define KS_ST 68
#define VS_ST 72
#define OFF_Q 0
#define OFF_K 8704                    // 128*68
#define OFF_V (OFF_K + 2 * 64 * KS_ST)
#define OFF_MSK (OFF_V + 2 * 64 * VS_ST)
#define FA_SMEM_BYTES ((OFF_MSK + 2 * 64) * 4)

__global__ __launch_bounds__(256, 1) void flash_kernel(
    const float* __restrict__ q, const float* __restrict__ k,
    const float* __restrict__ v, const int* __restrict__ mask,
    float* __restrict__ attn)
{
    extern __shared__ float smem[];
    const int tid = threadIdx.x, lane = tid & 31, wid = tid >> 5;
    const int z = blockIdx.y;
    const int b = z / H_, h = z % H_;
    const int qBase = blockIdx.x * 128;
    const float* Qg = q + (size_t)b * S_ * D_ + h * DK_;
    const float* Kg = k + (size_t)b * S_ * D_ + h * DK_;
    const float* Vg = v + (size_t)b * S_ * D_ + h * DK_;
    const uint32_t sb = smem_u32(smem);

    // Q tile: 128 rows x 64 floats = 2048 float4
    #pragma unroll
    for (int i = 0; i < 8; i++) {
        int idx = tid + i * 256;
        int r = idx >> 4, c4 = idx & 15;
        cp_async16(sb + (uint32_t)(OFF_Q + r * QS_ST + c4 * 4) * 4u,
                   Qg + (size_t)(qBase + r) * D_ + c4 * 4);
    }
    cp_commit();

    auto load_tile = [&](int c) {
        const int s = c & 1;
        const int kv0 = c * FA_BKV;
        const uint32_t ks = sb + (uint32_t)(OFF_K + s * (FA_BKV * KS_ST)) * 4u;
        const uint32_t vs = sb + (uint32_t)(OFF_V + s * (FA_BKV * VS_ST)) * 4u;
        #pragma unroll
        for (int i = 0; i < 4; i++) {
            int idx = tid + i * 256;
            int r = idx >> 4, c4 = idx & 15;
            cp_async16(ks + (uint32_t)(r * KS_ST + c4 * 4) * 4u,
                       Kg + (size_t)(kv0 + r) * D_ + c4 * 4);
            cp_async16(vs + (uint32_t)(r * VS_ST + c4 * 4) * 4u,
                       Vg + (size_t)(kv0 + r) * D_ + c4 * 4);
        }
        if (tid < FA_BKV)
            smem[OFF_MSK + s * FA_BKV + tid] = (mask[b * S_ + kv0 + tid] == 0) ? -1e30f : 0.0f;
    };

    load_tile(0);
    cp_commit();

    float m0 = -1e30f, m1 = -1e30f, l0 = 0.f, l1 = 0.f;
    float oacc[8][4];
    #pragma unroll
    for (int nt = 0; nt < 8; nt++)
        #pragma unroll
        for (int i = 0; i < 4; i++) oacc[nt][i] = 0.f;

    uint32_t qf[8][4];
    const int wrow = wid * 16;
    float* Pw = smem + OFF_Q + wrow * QS_ST;     // warp-private P (reuses this warp's Q rows)
    const int NKV = S_ / FA_BKV;

    for (int c = 0; c < NKV; c++) {
        if (c + 1 < NKV) load_tile(c + 1);
        cp_commit();
        cp_wait<1>();
        __syncthreads();

        if (c == 0) {
            const float* Qs = smem + OFF_Q;
            #pragma unroll
            for (int ks = 0; ks < 8; ks++) {
                const int r = wrow + (lane >> 2);
                const int cc = ks * 8 + (lane & 3);
                qf[ks][0] = __float_as_uint(Qs[r * QS_ST + cc]);
                qf[ks][1] = __float_as_uint(Qs[(r + 8) * QS_ST + cc]);
                qf[ks][2] = __float_as_uint(Qs[r * QS_ST + cc + 4]);
                qf[ks][3] = __float_as_uint(Qs[(r + 8) * QS_ST + cc + 4]);
            }
            __syncwarp();
        }

        const float* Ks = smem + OFF_K + (c & 1) * (FA_BKV * KS_ST);
        const float* Vs = smem + OFF_V + (c & 1) * (FA_BKV * VS_ST);
        const float* msk = smem + OFF_MSK + (c & 1) * FA_BKV;

        // ---- S = Q K^T ----
        float sacc[8][4];
        #pragma unroll
        for (int nt = 0; nt < 8; nt++)
            #pragma unroll
            for (int i = 0; i < 4; i++) sacc[nt][i] = 0.f;

        #pragma unroll
        for (int ks = 0; ks < 8; ks++) {
            const int kk = ks * 8 + (lane & 3);
            #pragma unroll
            for (int nt = 0; nt < 8; nt++) {
                const int n = nt * 8 + (lane >> 2);
                uint32_t bf[2];
                bf[0] = __float_as_uint(Ks[n * KS_ST + kk]);
                bf[1] = __float_as_uint(Ks[n * KS_ST + kk + 4]);
                mma_m16n8k8(sacc[nt], qf[ks], bf);
            }
        }

        // ---- scale + mask + row max ----
        float tm0 = -1e30f, tm1 = -1e30f;
        #pragma unroll
        for (int nt = 0; nt < 8; nt++) {
            const float ma = msk[nt * 8 + 2 * (lane & 3)];
            const float mb = msk[nt * 8 + 2 * (lane & 3) + 1];
            sacc[nt][0] = sacc[nt][0] * 0.125f + ma;
            sacc[nt][1] = sacc[nt][1] * 0.125f + mb;
            sacc[nt][2] = sacc[nt][2] * 0.125f + ma;
            sacc[nt][3] = sacc[nt][3] * 0.125f + mb;
            tm0 = fmaxf(tm0, fmaxf(sacc[nt][0], sacc[nt][1]));
            tm1 = fmaxf(tm1, fmaxf(sacc[nt][2], sacc[nt][3]));
        }
        tm0 = fmaxf(tm0, __shfl_xor_sync(0xffffffffu, tm0, 1));
        tm0 = fmaxf(tm0, __shfl_xor_sync(0xffffffffu, tm0, 2));
        tm1 = fmaxf(tm1, __shfl_xor_sync(0xffffffffu, tm1, 1));
        tm1 = fmaxf(tm1, __shfl_xor_sync(0xffffffffu, tm1, 2));

        const float mn0 = fmaxf(m0, tm0), mn1 = fmaxf(m1, tm1);
        const float a0 = __expf(m0 - mn0), a1 = __expf(m1 - mn1);
        m0 = mn0; m1 = mn1;

        // ---- p = exp(s - m), store tf32 P, row sums ----
        float rs0 = 0.f, rs1 = 0.f;
        const int pr = lane >> 2;
        #pragma unroll
        for (int nt = 0; nt < 8; nt++) {
            const float p0 = __expf(sacc[nt][0] - mn0);
            const float p1 = __expf(sacc[nt][1] - mn0);
            const float p2 = __expf(sacc[nt][2] - mn1);
            const float p3 = __expf(sacc[nt][3] - mn1);
            rs0 += p0 + p1; rs1 += p2 + p3;
            const int col = nt * 8 + 2 * (lane & 3);
            Pw[pr * QS_ST + col]           = to_tf32(p0);
            Pw[pr * QS_ST + col + 1]       = to_tf32(p1);
            Pw[(pr + 8) * QS_ST + col]     = to_tf32(p2);
            Pw[(pr + 8) * QS_ST + col + 1] = to_tf32(p3);
        }
        rs0 += __shfl_xor_sync(0xffffffffu, rs0, 1);
        rs0 += __shfl_xor_sync(0xffffffffu, rs0, 2);
        rs1 += __shfl_xor_sync(0xffffffffu, rs1, 1);
        rs1 += __shfl_xor_sync(0xffffffffu, rs1, 2);
        l0 = l0 * a0 + rs0;
        l1 = l1 * a1 + rs1;

        #pragma unroll
        for (int nt = 0; nt < 8; nt++) {
            oacc[nt][0] *= a0; oacc[nt][1] *= a0;
            oacc[nt][2] *= a1; oacc[nt][3] *= a1;
        }
        __syncwarp();

        // ---- O += P V ----
        #pragma unroll
        for (int ks = 0; ks < 8; ks++) {
            const int kk = ks * 8 + (lane & 3);
            uint32_t af[4];
            af[0] = __float_as_uint(Pw[pr * QS_ST + kk]);
            af[1] = __float_as_uint(Pw[(pr + 8) * QS_ST + kk]);
            af[2] = __float_as_uint(Pw[pr * QS_ST + kk + 4]);
            af[3] = __float_as_uint(Pw[(pr + 8) * QS_ST + kk + 4]);
            #pragma unroll
            for (int nt = 0; nt < 8; nt++) {
                const int n = nt * 8 + (lane >> 2);
                uint32_t bf[2];
                bf[0] = __float_as_uint(Vs[kk * VS_ST + n]);
                bf[1] = __float_as_uint(Vs[(kk + 4) * VS_ST + n]);
                mma_m16n8k8(oacc[nt], af, bf);
            }
        }
        __syncthreads();
    }

    // ---- epilogue: attn = tf32(O / l) ----
    const float inv0 = 1.0f / l0, inv1 = 1.0f / l1;
    const int r0 = qBase + wrow + (lane >> 2);
    float* Og = attn + (size_t)b * S_ * D_ + h * DK_;
    #pragma unroll
    for (int nt = 0; nt < 8; nt++) {
        const int col = nt * 8 + 2 * (lane & 3);
        float2 p0 = make_float2(to_tf32(oacc[nt][0] * inv0), to_tf32(oacc[nt][1] * inv0));
        float2 p1 = make_float2(to_tf32(oacc[nt][2] * inv1), to_tf32(oacc[nt][3] * inv1));
        *(float2*)(Og + (size_t)r0 * D_ + col) = p0;
        *(float2*)(Og + (size_t)(r0 + 8) * D_ + col) = p1;
    }
}

// ================= weight transpose + tf32 round: W[K,N] -> Wt[N,K] =================
__global__ __launch_bounds__(256) void transpose_tf32_kernel(
    const float* __restrict__ W, float* __restrict__ Wt, int Kd, int Nd)
{
    __shared__ float t[32][33];
    const int k0 = blockIdx.y * 32, n0 = blockIdx.x * 32;
    const int tx = threadIdx.x & 31, ty = threadIdx.x >> 5;
    #pragma unroll
    for (int i = 0; i < 32; i += 8)
        t[ty + i][tx] = W[(size_t)(k0 + ty + i) * Nd + n0 + tx];
    __syncthreads();
    #pragma unroll
    for (int i = 0; i < 32; i += 8)
        Wt[(size_t)(n0 + ty + i) * Kd + k0 + tx] = to_tf32(t[tx][ty + i]);
}

// ================= LayerNorm (ddof=1, /(std+eps)), tf32-rounded output =================
template<bool ROUND>
__global__ __launch_bounds__(256) void ln_kernel(
    const float* __restrict__ x, const float* __restrict__ w,
    const float* __restrict__ b, float* __restrict__ y)
{
    __shared__ float red[256];
    const int row = blockIdx.x;
    const int tid = threadIdx.x;
    const float* xr = x + (size_t)row * D_;
    float v0 = xr[tid], v1 = xr[tid + 256], v2 = xr[tid + 512], v3 = xr[tid + 768];

    red[tid] = v0 + v1 + v2 + v3; __syncthreads();
    for (int off = 128; off > 0; off >>= 1) {
        if (tid < off) red[tid] += red[tid + off];
        __syncthreads();
    }
    float mean = red[0] * (1.0f / D_);
    __syncthreads();

    float d0 = v0 - mean, d1 = v1 - mean, d2 = v2 - mean, d3 = v3 - mean;
    red[tid] = d0 * d0 + d1 * d1 + d2 * d2 + d3 * d3; __syncthreads();
    for (int off = 128; off > 0; off >>= 1) {
        if (tid < off) red[tid] += red[tid + off];
        __syncthreads();
    }
    float std1 = sqrtf(red[0] / (float)(D_ - 1));
    float rinv = 1.0f / (std1 + EPS_);

    float* yr = y + (size_t)row * D_;
    float o0 = w[tid] * d0 * rinv + b[tid];
    float o1 = w[tid + 256] * d1 * rinv + b[tid + 256];
    float o2 = w[tid + 512] * d2 * rinv + b[tid + 512];
    float o3 = w[tid + 768] * d3 * rinv + b[tid + 768];
    if (ROUND) { o0 = to_tf32(o0); o1 = to_tf32(o1); o2 = to_tf32(o2); o3 = to_tf32(o3); }
    yr[tid] = o0; yr[tid + 256] = o1; yr[tid + 512] = o2; yr[tid + 768] = o3;
}

// ================= host launcher =================
extern "C" void kernel_launch(void* const* d_in, const int* in_sizes, int n_in,
                              void* d_out, int out_size)
{
    const float* x    = (const float*)d_in[0];
    const int*   mask = (const int*)  d_in[1];
    const float* wq   = (const float*)d_in[2];
    const float* bq   = (const float*)d_in[3];
    const float* wk   = (const float*)d_in[4];
    const float* bk   = (const float*)d_in[5];
    const float* wv   = (const float*)d_in[6];
    const float* bv   = (const float*)d_in[7];
    const float* wo   = (const float*)d_in[8];
    const float* bo   = (const float*)d_in[9];
    const float* w1   = (const float*)d_in[10];
    const float* b1   = (const float*)d_in[11];
    const float* w2   = (const float*)d_in[12];
    const float* b2   = (const float*)d_in[13];
    const float* ln1w = (const float*)d_in[14];
    const float* ln1b = (const float*)d_in[15];
    const float* ln2w = (const float*)d_in[16];
    const float* ln2b = (const float*)d_in[17];
    float* out = (float*)d_out;

    float *xn, *q, *k, *v, *attn, *x1, *hbuf;
    float *wqT, *wkT, *wvT, *woT, *w1T, *w2T;
    cudaGetSymbolAddress((void**)&xn,   g_xn);
    cudaGetSymbolAddress((void**)&q,    g_q);
    cudaGetSymbolAddress((void**)&k,    g_k);
    cudaGetSymbolAddress((void**)&v,    g_v);
    cudaGetSymbolAddress((void**)&attn, g_attn);
    cudaGetSymbolAddress((void**)&x1,   g_x1);
    cudaGetSymbolAddress((void**)&hbuf, g_h);
    cudaGetSymbolAddress((void**)&wqT,  g_wqT);
    cudaGetSymbolAddress((void**)&wkT,  g_wkT);
    cudaGetSymbolAddress((void**)&wvT,  g_wvT);
    cudaGetSymbolAddress((void**)&woT,  g_woT);
    cudaGetSymbolAddress((void**)&w1T,  g_w1T);
    cudaGetSymbolAddress((void**)&w2T,  g_w2T);

    auto kQKV  = mma_gemm<true, false, false, true>;   // bias + tf32 round
    auto kRES  = mma_gemm<true, false, true,  false>;  // bias + residual
    auto kFFN1 = mma_gemm<true, true,  false, true>;   // bias + relu + round

    const int SM128 = 2 * (128 + 128) * RS * 4;        // 73728
    cudaFuncSetAttribute(kQKV,  cudaFuncAttributeMaxDynamicSharedMemorySize, SM128);
    cudaFuncSetAttribute(kRES,  cudaFuncAttributeMaxDynamicSharedMemorySize, SM128);
    cudaFuncSetAttribute(kFFN1, cudaFuncAttributeMaxDynamicSharedMemorySize, SM128);
    cudaFuncSetAttribute(flash_kernel, cudaFuncAttributeMaxDynamicSharedMemorySize, FA_SMEM_BYTES);

    // weight transposes (+ tf32 rounding)
    {
        dim3 gT(D_ / 32, D_ / 32);
        transpose_tf32_kernel<<<gT, 256>>>(wq, wqT, D_, D_);
        transpose_tf32_kernel<<<gT, 256>>>(wk, wkT, D_, D_);
        transpose_tf32_kernel<<<gT, 256>>>(wv, wvT, D_, D_);
        transpose_tf32_kernel<<<gT, 256>>>(wo, woT, D_, D_);
        dim3 gT1(DFF_ / 32, D_ / 32);
        transpose_tf32_kernel<<<gT1, 256>>>(w1, w1T, D_, DFF_);
        dim3 gT2(D_ / 32, DFF_ / 32);
        transpose_tf32_kernel<<<gT2, 256>>>(w2, w2T, DFF_, D_);
    }

    // 1) LN1 (tf32-rounded)
    ln_kernel<true><<<NTOK, 256>>>(x, ln1w, ln1b, xn);

    // 2) QKV projections (q,k,v tf32-rounded)
    dim3 gProj(D_ / 128, NTOK / 128);
    kQKV<<<gProj, 256, SM128>>>(xn, wqT, bq, nullptr, q, NTOK, D_, D_, D_, D_, D_);
    kQKV<<<gProj, 256, SM128>>>(xn, wkT, bk, nullptr, k, NTOK, D_, D_, D_, D_, D_);
    kQKV<<<gProj, 256, SM128>>>(xn, wvT, bv, nullptr, v, NTOK, D_, D_, D_, D_, D_);

    // 3) flash attention: attn = softmax(QK^T/8 + mask) @ V  (tf32-rounded)
    dim3 gFA(S_ / 128, NBH);
    flash_kernel<<<gFA, 256, FA_SMEM_BYTES>>>(q, k, v, mask, attn);

    // 4) x1 = x + attn @ wo + bo
    kRES<<<gProj, 256, SM128>>>(attn, woT, bo, x, x1, NTOK, D_, D_, D_, D_, D_);

    // 5) LN2 (tf32-rounded)
    ln_kernel<true><<<NTOK, 256>>>(x1, ln2w, ln2b, xn);

    // 6) h = relu(xn @ w1 + b1) (tf32-rounded)
    dim3 gF1(DFF_ / 128, NTOK / 128);
    kFFN1<<<gF1, 256, SM128>>>(xn, w1T, b1, nullptr, hbuf, NTOK, DFF_, D_, D_, D_, DFF_);

    // 7) out = x1 + h @ w2 + b2
    kRES<<<gProj, 256, SM128>>>(hbuf, w2T, b2, x1, out, NTOK, D_, DFF_, DFF_, DFF_, D_);
}

// round 6
// speedup vs baseline: 6.7407x; 1.8485x over previous
#include <cuda_runtime.h>
#include <cuda_fp16.h>
#include <cstdint>
#include <cstddef>

#define B_ 4
#define S_ 2048
#define D_ 1024
#define H_ 16
#define DK_ 64
#define DFF_ 4096
#define EPS_ 1e-6f
#define NTOK (B_ * S_)          // 8192
#define NBH  (B_ * H_)          // 64

// ================= scratch (device globals; no runtime allocation) =================
__device__ __half g_xn_h[(size_t)NTOK * D_];
__device__ float  g_q[(size_t)NTOK * D_];
__device__ float  g_k[(size_t)NTOK * D_];
__device__ float  g_v[(size_t)NTOK * D_];
__device__ __half g_attn_h[(size_t)NTOK * D_];
__device__ float  g_x1[(size_t)NTOK * D_];
__device__ __half g_h_h[(size_t)NTOK * DFF_];
// transposed fp16 weights: [N, K] K-major
__device__ __half g_wqT[(size_t)D_ * D_];
__device__ __half g_wkT[(size_t)D_ * D_];
__device__ __half g_wvT[(size_t)D_ * D_];
__device__ __half g_woT[(size_t)D_ * D_];
__device__ __half g_w1T[(size_t)DFF_ * D_];
__device__ __half g_w2T[(size_t)D_ * DFF_];

// ================= helpers =================
__device__ __forceinline__ uint32_t smem_u32(const void* p) {
    uint32_t a;
    asm("{ .reg .u64 t; cvta.to.shared.u64 t, %1; cvt.u32.u64 %0, t; }" : "=r"(a) : "l"(p));
    return a;
}
__device__ __forceinline__ float to_tf32(float x) {
    uint32_t u;
    asm("cvt.rna.tf32.f32 %0, %1;" : "=r"(u) : "f"(x));
    return __uint_as_float(u);
}
__device__ __forceinline__ void cp_async16(uint32_t smem, const void* g) {
    asm volatile("cp.async.cg.shared.global [%0], [%1], 16;" :: "r"(smem), "l"(g));
}
__device__ __forceinline__ void cp_commit() { asm volatile("cp.async.commit_group;" ::: "memory"); }
template <int N>
__device__ __forceinline__ void cp_wait() { asm volatile("cp.async.wait_group %0;" :: "n"(N) : "memory"); }

__device__ __forceinline__ void ldsm_x4(uint32_t r[4], uint32_t addr) {
    asm volatile("ldmatrix.sync.aligned.m8n8.x4.shared.b16 {%0,%1,%2,%3}, [%4];"
        : "=r"(r[0]), "=r"(r[1]), "=r"(r[2]), "=r"(r[3]) : "r"(addr));
}

// fp16 m16n8k16 mma, fp32 accum
__device__ __forceinline__ void mma_f16(float d[4], const uint32_t a[4], const uint32_t b[2]) {
    asm volatile(
        "mma.sync.aligned.m16n8k16.row.col.f32.f16.f16.f32 "
        "{%0,%1,%2,%3}, {%4,%5,%6,%7}, {%8,%9}, {%0,%1,%2,%3};"
        : "+f"(d[0]), "+f"(d[1]), "+f"(d[2]), "+f"(d[3])
        : "r"(a[0]), "r"(a[1]), "r"(a[2]), "r"(a[3]), "r"(b[0]), "r"(b[1]));
}

// tf32 m16n8k8 mma (flash attention)
__device__ __forceinline__ void mma_m16n8k8(float d[4], const uint32_t a[4], const uint32_t b[2]) {
    asm volatile(
        "mma.sync.aligned.m16n8k8.row.col.f32.tf32.tf32.f32 "
        "{%0,%1,%2,%3}, {%4,%5,%6,%7}, {%8,%9}, {%0,%1,%2,%3};"
        : "+f"(d[0]), "+f"(d[1]), "+f"(d[2]), "+f"(d[3])
        : "r"(a[0]), "r"(a[1]), "r"(a[2]), "r"(a[3]), "r"(b[0]), "r"(b[1]));
}

// ================= fp16 tensor GEMM: C[M,N] = A[M,K] @ Bt[N,K]^T =================
// BM=128, BN=128, BK=64. SMEM rows of 64 halves (128B) with XOR-16B swizzle.
// 256 threads, 8 warps, warp tile 32x64. ldmatrix fragment loads.
#define HG_STAGE_BYTES 32768                 // A 16KB + B 16KB
#define HG_SMEM_BYTES  (2 * HG_STAGE_BYTES)  // 64KB

template<bool HAS_BIAS, bool RELU, bool HAS_RES, bool ROUND_TF32, bool OUT_HALF>
__global__ __launch_bounds__(256) void hgemm(
    const __half* __restrict__ A, const __half* __restrict__ Bt,
    const float* __restrict__ bias, const float* __restrict__ res,
    void* __restrict__ Cv, int M, int N, int K, int lda, int ldb, int ldc)
{
    extern __shared__ char smem_raw[];
    const uint32_t sbase = smem_u32(smem_raw);

    const int tid = threadIdx.x, lane = tid & 31, wid = tid >> 5;
    const int wrow = (wid & 3) * 32;
    const int wcol = (wid >> 2) * 64;
    const int rowBase = blockIdx.y * 128;
    const int colBase = blockIdx.x * 128;

    auto load_chunk = [&](int c) {
        const uint32_t ast = sbase + (uint32_t)(c & 1) * HG_STAGE_BYTES;
        const uint32_t bst = ast + 16384;
        const int kOff = c * 64;
        #pragma unroll
        for (int i = 0; i < 4; i++) {                 // A: 128 rows x 8 chunks of 16B
            int g = tid + i * 256;
            int r = g >> 3, cc = g & 7;
            cp_async16(ast + r * 128 + (((cc ^ (r & 7))) << 4),
                       A + (size_t)(rowBase + r) * lda + kOff + cc * 8);
        }
        #pragma unroll
        for (int i = 0; i < 4; i++) {                 // B: 128 rows x 8 chunks
            int g = tid + i * 256;
            int r = g >> 3, cc = g & 7;
            cp_async16(bst + r * 128 + (((cc ^ (r & 7))) << 4),
                       Bt + (size_t)(colBase + r) * ldb + kOff + cc * 8);
        }
    };

    float acc[2][8][4];
    #pragma unroll
    for (int mt = 0; mt < 2; mt++)
        #pragma unroll
        for (int nt = 0; nt < 8; nt++)
            #pragma unroll
            for (int i = 0; i < 4; i++) acc[mt][nt][i] = 0.f;

    const int NC = K / 64;
    load_chunk(0); cp_commit();

    // lane-constant pieces of ldmatrix addresses
    const int arow = wrow + (lane & 15);          // A fragment row (within tile)
    const int ahi  = lane >> 4;                   // A chunk +0/+1 within k16
    const int brow = wcol + (lane & 7) + ((lane >> 4) << 3);   // B fragment n-row
    const int bhi  = (lane >> 3) & 1;             // B chunk +0/+1

    for (int c = 0; c < NC; c++) {
        if (c + 1 < NC) load_chunk(c + 1);
        cp_commit();
        cp_wait<1>();
        __syncthreads();

        const uint32_t ast = sbase + (uint32_t)(c & 1) * HG_STAGE_BYTES;
        const uint32_t bst = ast + 16384;

        uint32_t aAddr[2], bAddr[4];
        int arx[2], brx[4];
        #pragma unroll
        for (int mt = 0; mt < 2; mt++) {
            const int r = arow + mt * 16;
            aAddr[mt] = ast + r * 128;
            arx[mt] = r & 7;
        }
        #pragma unroll
        for (int np = 0; np < 4; np++) {
            const int n = brow + np * 16;
            bAddr[np] = bst + n * 128;
            brx[np] = n & 7;
        }

        #pragma unroll
        for (int ks = 0; ks < 4; ks++) {
            uint32_t af[2][4];
            #pragma unroll
            for (int mt = 0; mt < 2; mt++)
                ldsm_x4(af[mt], aAddr[mt] + (((2 * ks + ahi) ^ arx[mt]) << 4));
            #pragma unroll
            for (int np = 0; np < 4; np++) {
                uint32_t bf[4];
                ldsm_x4(bf, bAddr[np] + (((2 * ks + bhi) ^ brx[np]) << 4));
                #pragma unroll
                for (int mt = 0; mt < 2; mt++) {
                    mma_f16(acc[mt][np * 2],     af[mt], bf);
                    mma_f16(acc[mt][np * 2 + 1], af[mt], bf + 2);
                }
            }
        }
        __syncthreads();
    }

    // ---- epilogue ----
    float* Cf = (float*)Cv;
    __half* Ch = (__half*)Cv;
    #pragma unroll
    for (int mt = 0; mt < 2; mt++) {
        const int r0 = rowBase + wrow + mt * 16 + (lane >> 2);
        #pragma unroll
        for (int nt = 0; nt < 8; nt++) {
            const int col = colBase + wcol + nt * 8 + 2 * (lane & 3);
            float vx0 = acc[mt][nt][0], vy0 = acc[mt][nt][1];
            float vx1 = acc[mt][nt][2], vy1 = acc[mt][nt][3];
            if (HAS_BIAS) {
                const float b0v = bias[col], b1v = bias[col + 1];
                vx0 += b0v; vy0 += b1v; vx1 += b0v; vy1 += b1v;
            }
            if (RELU) {
                vx0 = fmaxf(vx0, 0.f); vy0 = fmaxf(vy0, 0.f);
                vx1 = fmaxf(vx1, 0.f); vy1 = fmaxf(vy1, 0.f);
            }
            if (HAS_RES) {
                vx0 += res[(size_t)r0 * ldc + col];
                vy0 += res[(size_t)r0 * ldc + col + 1];
                vx1 += res[(size_t)(r0 + 8) * ldc + col];
                vy1 += res[(size_t)(r0 + 8) * ldc + col + 1];
            }
            if (OUT_HALF) {
                *(__half2*)(Ch + (size_t)r0 * ldc + col) = __floats2half2_rn(vx0, vy0);
                *(__half2*)(Ch + (size_t)(r0 + 8) * ldc + col) = __floats2half2_rn(vx1, vy1);
            } else {
                if (ROUND_TF32) {
                    vx0 = to_tf32(vx0); vy0 = to_tf32(vy0);
                    vx1 = to_tf32(vx1); vy1 = to_tf32(vy1);
                }
                *(float2*)(Cf + (size_t)r0 * ldc + col) = make_float2(vx0, vy0);
                *(float2*)(Cf + (size_t)(r0 + 8) * ldc + col) = make_float2(vx1, vy1);
            }
        }
    }
}

// ================= flash attention (tf32 mma, online softmax) =================
#define FA_BKV 64
#define QS_ST 68
#define KS_ST 68
#define VS_ST 72
#define OFF_Q 0
#define OFF_K 8704
#define OFF_V (OFF_K + 2 * 64 * KS_ST)
#define OFF_MSK (OFF_V + 2 * 64 * VS_ST)
#define FA_SMEM_BYTES ((OFF_MSK + 2 * 64) * 4)

__global__ __launch_bounds__(256, 1) void flash_kernel(
    const float* __restrict__ q, const float* __restrict__ k,
    const float* __restrict__ v, const int* __restrict__ mask,
    __half* __restrict__ attn)
{
    extern __shared__ float smem[];
    const int tid = threadIdx.x, lane = tid & 31, wid = tid >> 5;
    const int z = blockIdx.y;
    const int b = z / H_, h = z % H_;
    const int qBase = blockIdx.x * 128;
    const float* Qg = q + (size_t)b * S_ * D_ + h * DK_;
    const float* Kg = k + (size_t)b * S_ * D_ + h * DK_;
    const float* Vg = v + (size_t)b * S_ * D_ + h * DK_;
    const uint32_t sb = smem_u32(smem);

    #pragma unroll
    for (int i = 0; i < 8; i++) {
        int idx = tid + i * 256;
        int r = idx >> 4, c4 = idx & 15;
        cp_async16(sb + (uint32_t)(OFF_Q + r * QS_ST + c4 * 4) * 4u,
                   Qg + (size_t)(qBase + r) * D_ + c4 * 4);
    }
    cp_commit();

    auto load_tile = [&](int c) {
        const int s = c & 1;
        const int kv0 = c * FA_BKV;
        const uint32_t ks = sb + (uint32_t)(OFF_K + s * (FA_BKV * KS_ST)) * 4u;
        const uint32_t vs = sb + (uint32_t)(OFF_V + s * (FA_BKV * VS_ST)) * 4u;
        #pragma unroll
        for (int i = 0; i < 4; i++) {
            int idx = tid + i * 256;
            int r = idx >> 4, c4 = idx & 15;
            cp_async16(ks + (uint32_t)(r * KS_ST + c4 * 4) * 4u,
                       Kg + (size_t)(kv0 + r) * D_ + c4 * 4);
            cp_async16(vs + (uint32_t)(r * VS_ST + c4 * 4) * 4u,
                       Vg + (size_t)(kv0 + r) * D_ + c4 * 4);
        }
        if (tid < FA_BKV)
            smem[OFF_MSK + s * FA_BKV + tid] = (mask[b * S_ + kv0 + tid] == 0) ? -1e30f : 0.0f;
    };

    load_tile(0);
    cp_commit();

    float m0 = -1e30f, m1 = -1e30f, l0 = 0.f, l1 = 0.f;
    float oacc[8][4];
    #pragma unroll
    for (int nt = 0; nt < 8; nt++)
        #pragma unroll
        for (int i = 0; i < 4; i++) oacc[nt][i] = 0.f;

    uint32_t qf[8][4];
    const int wrow = wid * 16;
    float* Pw = smem + OFF_Q + wrow * QS_ST;
    const int NKV = S_ / FA_BKV;

    for (int c = 0; c < NKV; c++) {
        if (c + 1 < NKV) load_tile(c + 1);
        cp_commit();
        cp_wait<1>();
        __syncthreads();

        if (c == 0) {
            const float* Qs = smem + OFF_Q;
            #pragma unroll
            for (int ks = 0; ks < 8; ks++) {
                const int r = wrow + (lane >> 2);
                const int cc = ks * 8 + (lane & 3);
                qf[ks][0] = __float_as_uint(Qs[r * QS_ST + cc]);
                qf[ks][1] = __float_as_uint(Qs[(r + 8) * QS_ST + cc]);
                qf[ks][2] = __float_as_uint(Qs[r * QS_ST + cc + 4]);
                qf[ks][3] = __float_as_uint(Qs[(r + 8) * QS_ST + cc + 4]);
            }
            __syncwarp();
        }

        const float* Ks = smem + OFF_K + (c & 1) * (FA_BKV * KS_ST);
        const float* Vs = smem + OFF_V + (c & 1) * (FA_BKV * VS_ST);
        const float* msk = smem + OFF_MSK + (c & 1) * FA_BKV;

        float sacc[8][4];
        #pragma unroll
        for (int nt = 0; nt < 8; nt++)
            #pragma unroll
            for (int i = 0; i < 4; i++) sacc[nt][i] = 0.f;

        #pragma unroll
        for (int ks = 0; ks < 8; ks++) {
            const int kk = ks * 8 + (lane & 3);
            #pragma unroll
            for (int nt = 0; nt < 8; nt++) {
                const int n = nt * 8 + (lane >> 2);
                uint32_t bf[2];
                bf[0] = __float_as_uint(Ks[n * KS_ST + kk]);
                bf[1] = __float_as_uint(Ks[n * KS_ST + kk + 4]);
                mma_m16n8k8(sacc[nt], qf[ks], bf);
            }
        }

        float tm0 = -1e30f, tm1 = -1e30f;
        #pragma unroll
        for (int nt = 0; nt < 8; nt++) {
            const float ma = msk[nt * 8 + 2 * (lane & 3)];
            const float mb = msk[nt * 8 + 2 * (lane & 3) + 1];
            sacc[nt][0] = sacc[nt][0] * 0.125f + ma;
            sacc[nt][1] = sacc[nt][1] * 0.125f + mb;
            sacc[nt][2] = sacc[nt][2] * 0.125f + ma;
            sacc[nt][3] = sacc[nt][3] * 0.125f + mb;
            tm0 = fmaxf(tm0, fmaxf(sacc[nt][0], sacc[nt][1]));
            tm1 = fmaxf(tm1, fmaxf(sacc[nt][2], sacc[nt][3]));
        }
        tm0 = fmaxf(tm0, __shfl_xor_sync(0xffffffffu, tm0, 1));
        tm0 = fmaxf(tm0, __shfl_xor_sync(0xffffffffu, tm0, 2));
        tm1 = fmaxf(tm1, __shfl_xor_sync(0xffffffffu, tm1, 1));
        tm1 = fmaxf(tm1, __shfl_xor_sync(0xffffffffu, tm1, 2));

        const float mn0 = fmaxf(m0, tm0), mn1 = fmaxf(m1, tm1);
        const float a0 = __expf(m0 - mn0), a1 = __expf(m1 - mn1);
        m0 = mn0; m1 = mn1;

        float rs0 = 0.f, rs1 = 0.f;
        const int pr = lane >> 2;
        #pragma unroll
        for (int nt = 0; nt < 8; nt++) {
            const float p0 = __expf(sacc[nt][0] - mn0);
            const float p1 = __expf(sacc[nt][1] - mn0);
            const float p2 = __expf(sacc[nt][2] - mn1);
            const float p3 = __expf(sacc[nt][3] - mn1);
            rs0 += p0 + p1; rs1 += p2 + p3;
            const int col = nt * 8 + 2 * (lane & 3);
            Pw[pr * QS_ST + col]           = to_tf32(p0);
            Pw[pr * QS_ST + col + 1]       = to_tf32(p1);
            Pw[(pr + 8) * QS_ST + col]     = to_tf32(p2);
            Pw[(pr + 8) * QS_ST + col + 1] = to_tf32(p3);
        }
        rs0 += __shfl_xor_sync(0xffffffffu, rs0, 1);
        rs0 += __shfl_xor_sync(0xffffffffu, rs0, 2);
        rs1 += __shfl_xor_sync(0xffffffffu, rs1, 1);
        rs1 += __shfl_xor_sync(0xffffffffu, rs1, 2);
        l0 = l0 * a0 + rs0;
        l1 = l1 * a1 + rs1;

        #pragma unroll
        for (int nt = 0; nt < 8; nt++) {
            oacc[nt][0] *= a0; oacc[nt][1] *= a0;
            oacc[nt][2] *= a1; oacc[nt][3] *= a1;
        }
        __syncwarp();

        #pragma unroll
        for (int ks = 0; ks < 8; ks++) {
            const int kk = ks * 8 + (lane & 3);
            uint32_t af[4];
            af[0] = __float_as_uint(Pw[pr * QS_ST + kk]);
            af[1] = __float_as_uint(Pw[(pr + 8) * QS_ST + kk]);
            af[2] = __float_as_uint(Pw[pr * QS_ST + kk + 4]);
            af[3] = __float_as_uint(Pw[(pr + 8) * QS_ST + kk + 4]);
            #pragma unroll
            for (int nt = 0; nt < 8; nt++) {
                const int n = nt * 8 + (lane >> 2);
                uint32_t bf[2];
                bf[0] = __float_as_uint(Vs[kk * VS_ST + n]);
                bf[1] = __float_as_uint(Vs[(kk + 4) * VS_ST + n]);
                mma_m16n8k8(oacc[nt], af, bf);
            }
        }
        __syncthreads();
    }

    // epilogue: attn = half(O / l)
    const float inv0 = 1.0f / l0, inv1 = 1.0f / l1;
    const int r0 = qBase + wrow + (lane >> 2);
    __half* Og = attn + (size_t)b * S_ * D_ + h * DK_;
    #pragma unroll
    for (int nt = 0; nt < 8; nt++) {
        const int col = nt * 8 + 2 * (lane & 3);
        *(__half2*)(Og + (size_t)r0 * D_ + col) =
            __floats2half2_rn(oacc[nt][0] * inv0, oacc[nt][1] * inv0);
        *(__half2*)(Og + (size_t)(r0 + 8) * D_ + col) =
            __floats2half2_rn(oacc[nt][2] * inv1, oacc[nt][3] * inv1);
    }
}

// ================= weight transpose -> fp16: W[K,N] -> Wt[N,K] =================
__global__ __launch_bounds__(256) void transpose_h_kernel(
    const float* __restrict__ W, __half* __restrict__ Wt, int Kd, int Nd)
{
    __shared__ float t[32][33];
    const int k0 = blockIdx.y * 32, n0 = blockIdx.x * 32;
    const int tx = threadIdx.x & 31, ty = threadIdx.x >> 5;
    #pragma unroll
    for (int i = 0; i < 32; i += 8)
        t[ty + i][tx] = W[(size_t)(k0 + ty + i) * Nd + n0 + tx];
    __syncthreads();
    #pragma unroll
    for (int i = 0; i < 32; i += 8)
        Wt[(size_t)(n0 + ty + i) * Kd + k0 + tx] = __float2half_rn(t[tx][ty + i]);
}

// ================= LayerNorm (ddof=1, /(std+eps)) -> fp16 output =================
__global__ __launch_bounds__(256) void ln_kernel(
    const float* __restrict__ x, const float* __restrict__ w,
    const float* __restrict__ b, __half* __restrict__ y)
{
    __shared__ float red[256];
    const int row = blockIdx.x;
    const int tid = threadIdx.x;
    const float* xr = x + (size_t)row * D_;
    float v0 = xr[tid], v1 = xr[tid + 256], v2 = xr[tid + 512], v3 = xr[tid + 768];

    red[tid] = v0 + v1 + v2 + v3; __syncthreads();
    for (int off = 128; off > 0; off >>= 1) {
        if (tid < off) red[tid] += red[tid + off];
        __syncthreads();
    }
    float mean = red[0] * (1.0f / D_);
    __syncthreads();

    float d0 = v0 - mean, d1 = v1 - mean, d2 = v2 - mean, d3 = v3 - mean;
    red[tid] = d0 * d0 + d1 * d1 + d2 * d2 + d3 * d3; __syncthreads();
    for (int off = 128; off > 0; off >>= 1) {
        if (tid < off) red[tid] += red[tid + off];
        __syncthreads();
    }
    float std1 = sqrtf(red[0] / (float)(D_ - 1));
    float rinv = 1.0f / (std1 + EPS_);

    __half* yr = y + (size_t)row * D_;
    yr[tid]       = __float2half_rn(w[tid]       * d0 * rinv + b[tid]);
    yr[tid + 256] = __float2half_rn(w[tid + 256] * d1 * rinv + b[tid + 256]);
    yr[tid + 512] = __float2half_rn(w[tid + 512] * d2 * rinv + b[tid + 512]);
    yr[tid + 768] = __float2half_rn(w[tid + 768] * d3 * rinv + b[tid + 768]);
}

// ================= host launcher =================
extern "C" void kernel_launch(void* const* d_in, const int* in_sizes, int n_in,
                              void* d_out, int out_size)
{
    const float* x    = (const float*)d_in[0];
    const int*   mask = (const int*)  d_in[1];
    const float* wq   = (const float*)d_in[2];
    const float* bq   = (const float*)d_in[3];
    const float* wk   = (const float*)d_in[4];
    const float* bk   = (const float*)d_in[5];
    const float* wv   = (const float*)d_in[6];
    const float* bv   = (const float*)d_in[7];
    const float* wo   = (const float*)d_in[8];
    const float* bo   = (const float*)d_in[9];
    const float* w1   = (const float*)d_in[10];
    const float* b1   = (const float*)d_in[11];
    const float* w2   = (const float*)d_in[12];
    const float* b2   = (const float*)d_in[13];
    const float* ln1w = (const float*)d_in[14];
    const float* ln1b = (const float*)d_in[15];
    const float* ln2w = (const float*)d_in[16];
    const float* ln2b = (const float*)d_in[17];
    float* out = (float*)d_out;

    __half *xn, *attn, *hbuf, *wqT, *wkT, *wvT, *woT, *w1T, *w2T;
    float *q, *k, *v, *x1;
    cudaGetSymbolAddress((void**)&xn,   g_xn_h);
    cudaGetSymbolAddress((void**)&q,    g_q);
    cudaGetSymbolAddress((void**)&k,    g_k);
    cudaGetSymbolAddress((void**)&v,    g_v);
    cudaGetSymbolAddress((void**)&attn, g_attn_h);
    cudaGetSymbolAddress((void**)&x1,   g_x1);
    cudaGetSymbolAddress((void**)&hbuf, g_h_h);
    cudaGetSymbolAddress((void**)&wqT,  g_wqT);
    cudaGetSymbolAddress((void**)&wkT,  g_wkT);
    cudaGetSymbolAddress((void**)&wvT,  g_wvT);
    cudaGetSymbolAddress((void**)&woT,  g_woT);
    cudaGetSymbolAddress((void**)&w1T,  g_w1T);
    cudaGetSymbolAddress((void**)&w2T,  g_w2T);

    // instantiations: <BIAS, RELU, RES, ROUND_TF32, OUT_HALF>
    auto kQKV  = hgemm<true, false, false, true,  false>;  // float out + tf32 round (feeds flash)
    auto kRES  = hgemm<true, false, true,  false, false>;  // float out + residual
    auto kFFN1 = hgemm<true, true,  false, false, true>;   // half out (feeds FFN2)

    cudaFuncSetAttribute(kQKV,  cudaFuncAttributeMaxDynamicSharedMemorySize, HG_SMEM_BYTES);
    cudaFuncSetAttribute(kRES,  cudaFuncAttributeMaxDynamicSharedMemorySize, HG_SMEM_BYTES);
    cudaFuncSetAttribute(kFFN1, cudaFuncAttributeMaxDynamicSharedMemorySize, HG_SMEM_BYTES);
    cudaFuncSetAttribute(flash_kernel, cudaFuncAttributeMaxDynamicSharedMemorySize, FA_SMEM_BYTES);

    // weight transposes (fp16)
    {
        dim3 gT(D_ / 32, D_ / 32);
        transpose_h_kernel<<<gT, 256>>>(wq, wqT, D_, D_);
        transpose_h_kernel<<<gT, 256>>>(wk, wkT, D_, D_);
        transpose_h_kernel<<<gT, 256>>>(wv, wvT, D_, D_);
        transpose_h_kernel<<<gT, 256>>>(wo, woT, D_, D_);
        dim3 gT1(DFF_ / 32, D_ / 32);
        transpose_h_kernel<<<gT1, 256>>>(w1, w1T, D_, DFF_);
        dim3 gT2(D_ / 32, DFF_ / 32);
        transpose_h_kernel<<<gT2, 256>>>(w2, w2T, DFF_, D_);
    }

    // 1) LN1 -> xn (half)
    ln_kernel<<<NTOK, 256>>>(x, ln1w, ln1b, xn);

    // 2) QKV projections (float out, tf32-rounded, feed flash)
    dim3 gProj(D_ / 128, NTOK / 128);
    kQKV<<<gProj, 256, HG_SMEM_BYTES>>>(xn, wqT, bq, nullptr, q, NTOK, D_, D_, D_, D_, D_);
    kQKV<<<gProj, 256, HG_SMEM_BYTES>>>(xn, wkT, bk, nullptr, k, NTOK, D_, D_, D_, D_, D_);
    kQKV<<<gProj, 256, HG_SMEM_BYTES>>>(xn, wvT, bv, nullptr, v, NTOK, D_, D_, D_, D_, D_);

    // 3) flash attention -> attn (half)
    dim3 gFA(S_ / 128, NBH);
    flash_kernel<<<gFA, 256, FA_SMEM_BYTES>>>(q, k, v, mask, attn);

    // 4) x1 = x + attn @ wo + bo  (float)
    kRES<<<gProj, 256, HG_SMEM_BYTES>>>(attn, woT, bo, x, x1, NTOK, D_, D_, D_, D_, D_);

    // 5) LN2 -> xn (half)
    ln_kernel<<<NTOK, 256>>>(x1, ln2w, ln2b, xn);

    // 6) h = relu(xn @ w1 + b1) -> half
    dim3 gF1(DFF_ / 128, NTOK / 128);
    kFFN1<<<gF1, 256, HG_SMEM_BYTES>>>(xn, w1T, b1, nullptr, hbuf, NTOK, DFF_, D_, D_, D_, DFF_);

    // 7) out = x1 + h @ w2 + b2  (float)
    kRES<<<gProj, 256, HG_SMEM_BYTES>>>(hbuf, w2T, b2, x1, out, NTOK, D_, DFF_, DFF_, DFF_, D_);
}

// round 7
// speedup vs baseline: 8.5844x; 1.2735x over previous
#include <cuda_runtime.h>
#include <cuda_fp16.h>
#include <cstdint>
#include <cstddef>

#define B_ 4
#define S_ 2048
#define D_ 1024
#define H_ 16
#define DK_ 64
#define DFF_ 4096
#define EPS_ 1e-6f
#define NTOK (B_ * S_)          // 8192
#define NBH  (B_ * H_)          // 64

// ================= scratch (device globals; no runtime allocation) =================
__device__ __half g_xn_h[(size_t)NTOK * D_];
__device__ __half g_q_h[(size_t)NTOK * D_];
__device__ __half g_k_h[(size_t)NTOK * D_];
__device__ __half g_v_h[(size_t)NTOK * D_];
__device__ __half g_attn_h[(size_t)NTOK * D_];
__device__ float  g_x1[(size_t)NTOK * D_];
__device__ __half g_h_h[(size_t)NTOK * DFF_];
// transposed fp16 weights: [N, K] K-major
__device__ __half g_wqT[(size_t)D_ * D_];
__device__ __half g_wkT[(size_t)D_ * D_];
__device__ __half g_wvT[(size_t)D_ * D_];
__device__ __half g_woT[(size_t)D_ * D_];
__device__ __half g_w1T[(size_t)DFF_ * D_];
__device__ __half g_w2T[(size_t)D_ * DFF_];

// ================= helpers =================
__device__ __forceinline__ uint32_t smem_u32(const void* p) {
    uint32_t a;
    asm("{ .reg .u64 t; cvta.to.shared.u64 t, %1; cvt.u32.u64 %0, t; }" : "=r"(a) : "l"(p));
    return a;
}
__device__ __forceinline__ void cp_async16(uint32_t smem, const void* g) {
    asm volatile("cp.async.cg.shared.global [%0], [%1], 16;" :: "r"(smem), "l"(g));
}
__device__ __forceinline__ void cp_commit() { asm volatile("cp.async.commit_group;" ::: "memory"); }
template <int N>
__device__ __forceinline__ void cp_wait() { asm volatile("cp.async.wait_group %0;" :: "n"(N) : "memory"); }

__device__ __forceinline__ void ldsm_x4(uint32_t r[4], uint32_t addr) {
    asm volatile("ldmatrix.sync.aligned.m8n8.x4.shared.b16 {%0,%1,%2,%3}, [%4];"
        : "=r"(r[0]), "=r"(r[1]), "=r"(r[2]), "=r"(r[3]) : "r"(addr));
}
__device__ __forceinline__ void ldsm_x4_t(uint32_t r[4], uint32_t addr) {
    asm volatile("ldmatrix.sync.aligned.m8n8.x4.trans.shared.b16 {%0,%1,%2,%3}, [%4];"
        : "=r"(r[0]), "=r"(r[1]), "=r"(r[2]), "=r"(r[3]) : "r"(addr));
}

// fp16 m16n8k16 mma, fp32 accum
__device__ __forceinline__ void mma_f16(float d[4], const uint32_t a[4], const uint32_t b[2]) {
    asm volatile(
        "mma.sync.aligned.m16n8k16.row.col.f32.f16.f16.f32 "
        "{%0,%1,%2,%3}, {%4,%5,%6,%7}, {%8,%9}, {%0,%1,%2,%3};"
        : "+f"(d[0]), "+f"(d[1]), "+f"(d[2]), "+f"(d[3])
        : "r"(a[0]), "r"(a[1]), "r"(a[2]), "r"(a[3]), "r"(b[0]), "r"(b[1]));
}

__device__ __forceinline__ uint32_t packh2(float a, float b) {
    __half2 h = __floats2half2_rn(a, b);
    return *(uint32_t*)&h;
}

// ================= fp16 tensor GEMM: C[M,N] = A[M,K] @ Bt[N,K]^T =================
#define HG_STAGE_BYTES 32768
#define HG_SMEM_BYTES  (2 * HG_STAGE_BYTES)

template<bool HAS_BIAS, bool RELU, bool HAS_RES, bool OUT_HALF>
__global__ __launch_bounds__(256) void hgemm(
    const __half* __restrict__ A, const __half* __restrict__ Bt,
    const float* __restrict__ bias, const float* __restrict__ res,
    void* __restrict__ Cv, int M, int N, int K, int lda, int ldb, int ldc)
{
    extern __shared__ char smem_raw[];
    const uint32_t sbase = smem_u32(smem_raw);

    const int tid = threadIdx.x, lane = tid & 31, wid = tid >> 5;
    const int wrow = (wid & 3) * 32;
    const int wcol = (wid >> 2) * 64;
    const int rowBase = blockIdx.y * 128;
    const int colBase = blockIdx.x * 128;

    auto load_chunk = [&](int c) {
        const uint32_t ast = sbase + (uint32_t)(c & 1) * HG_STAGE_BYTES;
        const uint32_t bst = ast + 16384;
        const int kOff = c * 64;
        #pragma unroll
        for (int i = 0; i < 4; i++) {
            int g = tid + i * 256;
            int r = g >> 3, cc = g & 7;
            cp_async16(ast + r * 128 + (((cc ^ (r & 7))) << 4),
                       A + (size_t)(rowBase + r) * lda + kOff + cc * 8);
        }
        #pragma unroll
        for (int i = 0; i < 4; i++) {
            int g = tid + i * 256;
            int r = g >> 3, cc = g & 7;
            cp_async16(bst + r * 128 + (((cc ^ (r & 7))) << 4),
                       Bt + (size_t)(colBase + r) * ldb + kOff + cc * 8);
        }
    };

    float acc[2][8][4];
    #pragma unroll
    for (int mt = 0; mt < 2; mt++)
        #pragma unroll
        for (int nt = 0; nt < 8; nt++)
            #pragma unroll
            for (int i = 0; i < 4; i++) acc[mt][nt][i] = 0.f;

    const int NC = K / 64;
    load_chunk(0); cp_commit();

    const int arow = wrow + (lane & 15);
    const int ahi  = lane >> 4;
    const int brow = wcol + (lane & 7) + ((lane >> 4) << 3);
    const int bhi  = (lane >> 3) & 1;

    for (int c = 0; c < NC; c++) {
        if (c + 1 < NC) load_chunk(c + 1);
        cp_commit();
        cp_wait<1>();
        __syncthreads();

        const uint32_t ast = sbase + (uint32_t)(c & 1) * HG_STAGE_BYTES;
        const uint32_t bst = ast + 16384;

        uint32_t aAddr[2], bAddr[4];
        int arx[2], brx[4];
        #pragma unroll
        for (int mt = 0; mt < 2; mt++) {
            const int r = arow + mt * 16;
            aAddr[mt] = ast + r * 128;
            arx[mt] = r & 7;
        }
        #pragma unroll
        for (int np = 0; np < 4; np++) {
            const int n = brow + np * 16;
            bAddr[np] = bst + n * 128;
            brx[np] = n & 7;
        }

        #pragma unroll
        for (int ks = 0; ks < 4; ks++) {
            uint32_t af[2][4];
            #pragma unroll
            for (int mt = 0; mt < 2; mt++)
                ldsm_x4(af[mt], aAddr[mt] + (((2 * ks + ahi) ^ arx[mt]) << 4));
            #pragma unroll
            for (int np = 0; np < 4; np++) {
                uint32_t bf[4];
                ldsm_x4(bf, bAddr[np] + (((2 * ks + bhi) ^ brx[np]) << 4));
                #pragma unroll
                for (int mt = 0; mt < 2; mt++) {
                    mma_f16(acc[mt][np * 2],     af[mt], bf);
                    mma_f16(acc[mt][np * 2 + 1], af[mt], bf + 2);
                }
            }
        }
        __syncthreads();
    }

    float* Cf = (float*)Cv;
    __half* Ch = (__half*)Cv;
    #pragma unroll
    for (int mt = 0; mt < 2; mt++) {
        const int r0 = rowBase + wrow + mt * 16 + (lane >> 2);
        #pragma unroll
        for (int nt = 0; nt < 8; nt++) {
            const int col = colBase + wcol + nt * 8 + 2 * (lane & 3);
            float vx0 = acc[mt][nt][0], vy0 = acc[mt][nt][1];
            float vx1 = acc[mt][nt][2], vy1 = acc[mt][nt][3];
            if (HAS_BIAS) {
                const float b0v = bias[col], b1v = bias[col + 1];
                vx0 += b0v; vy0 += b1v; vx1 += b0v; vy1 += b1v;
            }
            if (RELU) {
                vx0 = fmaxf(vx0, 0.f); vy0 = fmaxf(vy0, 0.f);
                vx1 = fmaxf(vx1, 0.f); vy1 = fmaxf(vy1, 0.f);
            }
            if (HAS_RES) {
                vx0 += res[(size_t)r0 * ldc + col];
                vy0 += res[(size_t)r0 * ldc + col + 1];
                vx1 += res[(size_t)(r0 + 8) * ldc + col];
                vy1 += res[(size_t)(r0 + 8) * ldc + col + 1];
            }
            if (OUT_HALF) {
                *(__half2*)(Ch + (size_t)r0 * ldc + col) = __floats2half2_rn(vx0, vy0);
                *(__half2*)(Ch + (size_t)(r0 + 8) * ldc + col) = __floats2half2_rn(vx1, vy1);
            } else {
                *(float2*)(Cf + (size_t)r0 * ldc + col) = make_float2(vx0, vy0);
                *(float2*)(Cf + (size_t)(r0 + 8) * ldc + col) = make_float2(vx1, vy1);
            }
        }
    }
}

// ================= fp16 flash attention (ldmatrix + register P) =================
// Q tile 128 x 64h (16KB swizzled), K/V 64 x 64h double-buffered (8KB/stage each).
#define OFF_K 16384
#define OFF_V (OFF_K + 2 * 8192)
#define OFF_MSK (OFF_V + 2 * 8192)
#define FA_SMEM_BYTES (OFF_MSK + 2 * 64 * 4)

__global__ __launch_bounds__(256, 1) void flash_h_kernel(
    const __half* __restrict__ q, const __half* __restrict__ k,
    const __half* __restrict__ v, const int* __restrict__ mask,
    __half* __restrict__ attn)
{
    extern __shared__ char smem_raw[];
    float* mskf = (float*)(smem_raw + OFF_MSK);
    const uint32_t sb = smem_u32(smem_raw);

    const int tid = threadIdx.x, lane = tid & 31, wid = tid >> 5;
    const int z = blockIdx.y;
    const int b = z / H_, h = z % H_;
    const int qBase = blockIdx.x * 128;
    const __half* Qg = q + (size_t)b * S_ * D_ + h * DK_;
    const __half* Kg = k + (size_t)b * S_ * D_ + h * DK_;
    const __half* Vg = v + (size_t)b * S_ * D_ + h * DK_;

    // Q: 128 rows x 8 chunks of 16B
    #pragma unroll
    for (int i = 0; i < 4; i++) {
        int g = tid + i * 256;
        int r = g >> 3, cc = g & 7;
        cp_async16(sb + r * 128 + (((cc ^ (r & 7))) << 4),
                   Qg + (size_t)(qBase + r) * D_ + cc * 8);
    }
    cp_commit();

    auto load_tile = [&](int c) {
        const int s = c & 1;
        const int kv0 = c * 64;
        const uint32_t kst = sb + OFF_K + s * 8192;
        const uint32_t vst = sb + OFF_V + s * 8192;
        #pragma unroll
        for (int i = 0; i < 2; i++) {
            int g = tid + i * 256;
            int r = g >> 3, cc = g & 7;
            uint32_t swz = r * 128 + (((cc ^ (r & 7))) << 4);
            cp_async16(kst + swz, Kg + (size_t)(kv0 + r) * D_ + cc * 8);
            cp_async16(vst + swz, Vg + (size_t)(kv0 + r) * D_ + cc * 8);
        }
        if (tid < 64)
            mskf[s * 64 + tid] = (mask[b * S_ + kv0 + tid] == 0) ? -1e30f : 0.0f;
    };

    load_tile(0);
    cp_commit();

    float m0 = -1e30f, m1 = -1e30f, l0 = 0.f, l1 = 0.f;
    float oacc[8][4];
    #pragma unroll
    for (int nt = 0; nt < 8; nt++)
        #pragma unroll
        for (int i = 0; i < 4; i++) oacc[nt][i] = 0.f;

    uint32_t qf[4][4];
    const int wrow = wid * 16;

    // lane-constant ldmatrix address pieces
    const int arow = wrow + (lane & 15);
    const int ahi  = lane >> 4;
    const int krow = (lane & 7) + ((lane >> 4) << 3);
    const int khi  = (lane >> 3) & 1;
    const int vg   = lane >> 3;
    const int vi   = lane & 7;

    const int NKV = S_ / 64;
    for (int c = 0; c < NKV; c++) {
        if (c + 1 < NKV) load_tile(c + 1);
        cp_commit();
        cp_wait<1>();
        __syncthreads();

        if (c == 0) {
            const int arx = arow & 7;
            #pragma unroll
            for (int ks = 0; ks < 4; ks++)
                ldsm_x4(qf[ks], sb + arow * 128 + (((2 * ks + ahi) ^ arx) << 4));
        }

        const uint32_t kst = sb + OFF_K + (c & 1) * 8192;
        const uint32_t vst = sb + OFF_V + (c & 1) * 8192;
        const float* msk = mskf + (c & 1) * 64;

        // ---- S = Q K^T (fp16 mma) ----
        float sacc[8][4];
        #pragma unroll
        for (int nt = 0; nt < 8; nt++)
            #pragma unroll
            for (int i = 0; i < 4; i++) sacc[nt][i] = 0.f;

        #pragma unroll
        for (int ks = 0; ks < 4; ks++) {
            #pragma unroll
            for (int ng = 0; ng < 4; ng++) {
                const int row = ng * 16 + krow;
                uint32_t bf[4];
                ldsm_x4(bf, kst + row * 128 + (((2 * ks + khi) ^ (row & 7)) << 4));
                mma_f16(sacc[ng * 2],     qf[ks], bf);
                mma_f16(sacc[ng * 2 + 1], qf[ks], bf + 2);
            }
        }

        // ---- scale + mask + row max ----
        float tm0 = -1e30f, tm1 = -1e30f;
        #pragma unroll
        for (int nt = 0; nt < 8; nt++) {
            const float ma = msk[nt * 8 + 2 * (lane & 3)];
            const float mb = msk[nt * 8 + 2 * (lane & 3) + 1];
            sacc[nt][0] = sacc[nt][0] * 0.125f + ma;
            sacc[nt][1] = sacc[nt][1] * 0.125f + mb;
            sacc[nt][2] = sacc[nt][2] * 0.125f + ma;
            sacc[nt][3] = sacc[nt][3] * 0.125f + mb;
            tm0 = fmaxf(tm0, fmaxf(sacc[nt][0], sacc[nt][1]));
            tm1 = fmaxf(tm1, fmaxf(sacc[nt][2], sacc[nt][3]));
        }
        tm0 = fmaxf(tm0, __shfl_xor_sync(0xffffffffu, tm0, 1));
        tm0 = fmaxf(tm0, __shfl_xor_sync(0xffffffffu, tm0, 2));
        tm1 = fmaxf(tm1, __shfl_xor_sync(0xffffffffu, tm1, 1));
        tm1 = fmaxf(tm1, __shfl_xor_sync(0xffffffffu, tm1, 2));

        const float mn0 = fmaxf(m0, tm0), mn1 = fmaxf(m1, tm1);
        const float a0 = __expf(m0 - mn0), a1 = __expf(m1 - mn1);
        m0 = mn0; m1 = mn1;

        // ---- p = exp(s - m) in registers, pack to fp16 A fragments ----
        float rs0 = 0.f, rs1 = 0.f;
        #pragma unroll
        for (int nt = 0; nt < 8; nt++) {
            sacc[nt][0] = __expf(sacc[nt][0] - mn0);
            sacc[nt][1] = __expf(sacc[nt][1] - mn0);
            sacc[nt][2] = __expf(sacc[nt][2] - mn1);
            sacc[nt][3] = __expf(sacc[nt][3] - mn1);
            rs0 += sacc[nt][0] + sacc[nt][1];
            rs1 += sacc[nt][2] + sacc[nt][3];
        }
        rs0 += __shfl_xor_sync(0xffffffffu, rs0, 1);
        rs0 += __shfl_xor_sync(0xffffffffu, rs0, 2);
        rs1 += __shfl_xor_sync(0xffffffffu, rs1, 1);
        rs1 += __shfl_xor_sync(0xffffffffu, rs1, 2);
        l0 = l0 * a0 + rs0;
        l1 = l1 * a1 + rs1;

        uint32_t pa[4][4];
        #pragma unroll
        for (int ks = 0; ks < 4; ks++) {
            pa[ks][0] = packh2(sacc[2 * ks][0],     sacc[2 * ks][1]);
            pa[ks][1] = packh2(sacc[2 * ks][2],     sacc[2 * ks][3]);
            pa[ks][2] = packh2(sacc[2 * ks + 1][0], sacc[2 * ks + 1][1]);
            pa[ks][3] = packh2(sacc[2 * ks + 1][2], sacc[2 * ks + 1][3]);
        }

        #pragma unroll
        for (int nt = 0; nt < 8; nt++) {
            oacc[nt][0] *= a0; oacc[nt][1] *= a0;
            oacc[nt][2] *= a1; oacc[nt][3] *= a1;
        }

        // ---- O += P V  (V via ldmatrix.trans) ----
        #pragma unroll
        for (int ks = 0; ks < 4; ks++) {
            #pragma unroll
            for (int ng = 0; ng < 4; ng++) {
                const int row = ks * 16 + 8 * (vg & 1) + vi;
                const int cc = ng * 2 + (vg >> 1);
                uint32_t bf[4];
                ldsm_x4_t(bf, vst + row * 128 + (((cc ^ (row & 7))) << 4));
                mma_f16(oacc[ng * 2],     pa[ks], bf);
                mma_f16(oacc[ng * 2 + 1], pa[ks], bf + 2);
            }
        }
        __syncthreads();
    }

    // ---- epilogue: attn = half(O / l) ----
    const float inv0 = 1.0f / l0, inv1 = 1.0f / l1;
    const int r0 = qBase + wrow + (lane >> 2);
    __half* Og = attn + (size_t)b * S_ * D_ + h * DK_;
    #pragma unroll
    for (int nt = 0; nt < 8; nt++) {
        const int col = nt * 8 + 2 * (lane & 3);
        *(__half2*)(Og + (size_t)r0 * D_ + col) =
            __floats2half2_rn(oacc[nt][0] * inv0, oacc[nt][1] * inv0);
        *(__half2*)(Og + (size_t)(r0 + 8) * D_ + col) =
            __floats2half2_rn(oacc[nt][2] * inv1, oacc[nt][3] * inv1);
    }
}

// ================= weight transpose -> fp16: W[K,N] -> Wt[N,K] =================
__global__ __launch_bounds__(256) void transpose_h_kernel(
    const float* __restrict__ W, __half* __restrict__ Wt, int Kd, int Nd)
{
    __shared__ float t[32][33];
    const int k0 = blockIdx.y * 32, n0 = blockIdx.x * 32;
    const int tx = threadIdx.x & 31, ty = threadIdx.x >> 5;
    #pragma unroll
    for (int i = 0; i < 32; i += 8)
        t[ty + i][tx] = W[(size_t)(k0 + ty + i) * Nd + n0 + tx];
    __syncthreads();
    #pragma unroll
    for (int i = 0; i < 32; i += 8)
        Wt[(size_t)(n0 + ty + i) * Kd + k0 + tx] = __float2half_rn(t[tx][ty + i]);
}

// ================= LayerNorm (ddof=1, /(std+eps)) -> fp16 output =================
__global__ __launch_bounds__(256) void ln_kernel(
    const float* __restrict__ x, const float* __restrict__ w,
    const float* __restrict__ b, __half* __restrict__ y)
{
    __shared__ float red[256];
    const int row = blockIdx.x;
    const int tid = threadIdx.x;
    const float* xr = x + (size_t)row * D_;
    float v0 = xr[tid], v1 = xr[tid + 256], v2 = xr[tid + 512], v3 = xr[tid + 768];

    red[tid] = v0 + v1 + v2 + v3; __syncthreads();
    for (int off = 128; off > 0; off >>= 1) {
        if (tid < off) red[tid] += red[tid + off];
        __syncthreads();
    }
    float mean = red[0] * (1.0f / D_);
    __syncthreads();

    float d0 = v0 - mean, d1 = v1 - mean, d2 = v2 - mean, d3 = v3 - mean;
    red[tid] = d0 * d0 + d1 * d1 + d2 * d2 + d3 * d3; __syncthreads();
    for (int off = 128; off > 0; off >>= 1) {
        if (tid < off) red[tid] += red[tid + off];
        __syncthreads();
    }
    float std1 = sqrtf(red[0] / (float)(D_ - 1));
    float rinv = 1.0f / (std1 + EPS_);

    __half* yr = y + (size_t)row * D_;
    yr[tid]       = __float2half_rn(w[tid]       * d0 * rinv + b[tid]);
    yr[tid + 256] = __float2half_rn(w[tid + 256] * d1 * rinv + b[tid + 256]);
    yr[tid + 512] = __float2half_rn(w[tid + 512] * d2 * rinv + b[tid + 512]);
    yr[tid + 768] = __float2half_rn(w[tid + 768] * d3 * rinv + b[tid + 768]);
}

// ================= host launcher =================
extern "C" void kernel_launch(void* const* d_in, const int* in_sizes, int n_in,
                              void* d_out, int out_size)
{
    const float* x    = (const float*)d_in[0];
    const int*   mask = (const int*)  d_in[1];
    const float* wq   = (const float*)d_in[2];
    const float* bq   = (const float*)d_in[3];
    const float* wk   = (const float*)d_in[4];
    const float* bk   = (const float*)d_in[5];
    const float* wv   = (const float*)d_in[6];
    const float* bv   = (const float*)d_in[7];
    const float* wo   = (const float*)d_in[8];
    const float* bo   = (const float*)d_in[9];
    const float* w1   = (const float*)d_in[10];
    const float* b1   = (const float*)d_in[11];
    const float* w2   = (const float*)d_in[12];
    const float* b2   = (const float*)d_in[13];
    const float* ln1w = (const float*)d_in[14];
    const float* ln1b = (const float*)d_in[15];
    const float* ln2w = (const float*)d_in[16];
    const float* ln2b = (const float*)d_in[17];
    float* out = (float*)d_out;

    __half *xn, *qh, *kh, *vh, *attn, *hbuf, *wqT, *wkT, *wvT, *woT, *w1T, *w2T;
    float *x1;
    cudaGetSymbolAddress((void**)&xn,   g_xn_h);
    cudaGetSymbolAddress((void**)&qh,   g_q_h);
    cudaGetSymbolAddress((void**)&kh,   g_k_h);
    cudaGetSymbolAddress((void**)&vh,   g_v_h);
    cudaGetSymbolAddress((void**)&attn, g_attn_h);
    cudaGetSymbolAddress((void**)&x1,   g_x1);
    cudaGetSymbolAddress((void**)&hbuf, g_h_h);
    cudaGetSymbolAddress((void**)&wqT,  g_wqT);
    cudaGetSymbolAddress((void**)&wkT,  g_wkT);
    cudaGetSymbolAddress((void**)&wvT,  g_wvT);
    cudaGetSymbolAddress((void**)&woT,  g_woT);
    cudaGetSymbolAddress((void**)&w1T,  g_w1T);
    cudaGetSymbolAddress((void**)&w2T,  g_w2T);

    // instantiations: <BIAS, RELU, RES, OUT_HALF>
    auto kQKV  = hgemm<true, false, false, true>;   // half out (feeds flash)
    auto kRES  = hgemm<true, false, true,  false>;  // float out + residual
    auto kFFN1 = hgemm<true, true,  false, true>;   // half out (feeds FFN2)

    cudaFuncSetAttribute(kQKV,  cudaFuncAttributeMaxDynamicSharedMemorySize, HG_SMEM_BYTES);
    cudaFuncSetAttribute(kRES,  cudaFuncAttributeMaxDynamicSharedMemorySize, HG_SMEM_BYTES);
    cudaFuncSetAttribute(kFFN1, cudaFuncAttributeMaxDynamicSharedMemorySize, HG_SMEM_BYTES);
    cudaFuncSetAttribute(flash_h_kernel, cudaFuncAttributeMaxDynamicSharedMemorySize, FA_SMEM_BYTES);

    // weight transposes (fp16)
    {
        dim3 gT(D_ / 32, D_ / 32);
        transpose_h_kernel<<<gT, 256>>>(wq, wqT, D_, D_);
        transpose_h_kernel<<<gT, 256>>>(wk, wkT, D_, D_);
        transpose_h_kernel<<<gT, 256>>>(wv, wvT, D_, D_);
        transpose_h_kernel<<<gT, 256>>>(wo, woT, D_, D_);
        dim3 gT1(DFF_ / 32, D_ / 32);
        transpose_h_kernel<<<gT1, 256>>>(w1, w1T, D_, DFF_);
        dim3 gT2(D_ / 32, DFF_ / 32);
        transpose_h_kernel<<<gT2, 256>>>(w2, w2T, DFF_, D_);
    }

    // 1) LN1 -> xn (half)
    ln_kernel<<<NTOK, 256>>>(x, ln1w, ln1b, xn);

    // 2) QKV projections -> half
    dim3 gProj(D_ / 128, NTOK / 128);
    kQKV<<<gProj, 256, HG_SMEM_BYTES>>>(xn, wqT, bq, nullptr, qh, NTOK, D_, D_, D_, D_, D_);
    kQKV<<<gProj, 256, HG_SMEM_BYTES>>>(xn, wkT, bk, nullptr, kh, NTOK, D_, D_, D_, D_, D_);
    kQKV<<<gProj, 256, HG_SMEM_BYTES>>>(xn, wvT, bv, nullptr, vh, NTOK, D_, D_, D_, D_, D_);

    // 3) fp16 flash attention -> attn (half)
    dim3 gFA(S_ / 128, NBH);
    flash_h_kernel<<<gFA, 256, FA_SMEM_BYTES>>>(qh, kh, vh, mask, attn);

    // 4) x1 = x + attn @ wo + bo  (float)
    kRES<<<gProj, 256, HG_SMEM_BYTES>>>(attn, woT, bo, x, x1, NTOK, D_, D_, D_, D_, D_);

    // 5) LN2 -> xn (half)
    ln_kernel<<<NTOK, 256>>>(x1, ln2w, ln2b, xn);

    // 6) h = relu(xn @ w1 + b1) -> half
    dim3 gF1(DFF_ / 128, NTOK / 128);
    kFFN1<<<gF1, 256, HG_SMEM_BYTES>>>(xn, w1T, b1, nullptr, hbuf, NTOK, DFF_, D_, D_, D_, DFF_);

    // 7) out = x1 + h @ w2 + b2  (float)
    kRES<<<gProj, 256, HG_SMEM_BYTES>>>(hbuf, w2T, b2, x1, out, NTOK, D_, DFF_, DFF_, DFF_, D_);
}

// round 8
// speedup vs baseline: 9.0149x; 1.0502x over previous
#include <cuda_runtime.h>
#include <cuda_fp16.h>
#include <cstdint>
#include <cstddef>

#define B_ 4
#define S_ 2048
#define D_ 1024
#define H_ 16
#define DK_ 64
#define DFF_ 4096
#define EPS_ 1e-6f
#define NTOK (B_ * S_)          // 8192
#define NBH  (B_ * H_)          // 64
#define QKV_LD (3 * D_)         // fused qkv row stride

// ================= scratch (device globals; no runtime allocation) =================
__device__ __half g_xn_h[(size_t)NTOK * D_];
__device__ __half g_qkv_h[(size_t)NTOK * 3 * D_];     // fused [NTOK, 3*D] = q|k|v
__device__ __half g_attn_h[(size_t)NTOK * D_];
__device__ float  g_x1[(size_t)NTOK * D_];
__device__ __half g_h_h[(size_t)NTOK * DFF_];
// fused transposed fp16 weights
__device__ __half g_wqkvT[(size_t)3 * D_ * D_];       // [3072, 1024] K-major
__device__ float  g_bqkv[3 * D_];
__device__ __half g_woT[(size_t)D_ * D_];
__device__ __half g_w1T[(size_t)DFF_ * D_];
__device__ __half g_w2T[(size_t)D_ * DFF_];

// ================= helpers =================
__device__ __forceinline__ uint32_t smem_u32(const void* p) {
    uint32_t a;
    asm("{ .reg .u64 t; cvta.to.shared.u64 t, %1; cvt.u32.u64 %0, t; }" : "=r"(a) : "l"(p));
    return a;
}
__device__ __forceinline__ void cp_async16(uint32_t smem, const void* g) {
    asm volatile("cp.async.cg.shared.global [%0], [%1], 16;" :: "r"(smem), "l"(g));
}
__device__ __forceinline__ void cp_commit() { asm volatile("cp.async.commit_group;" ::: "memory"); }
template <int N>
__device__ __forceinline__ void cp_wait() { asm volatile("cp.async.wait_group %0;" :: "n"(N) : "memory"); }

__device__ __forceinline__ void ldsm_x4(uint32_t r[4], uint32_t addr) {
    asm volatile("ldmatrix.sync.aligned.m8n8.x4.shared.b16 {%0,%1,%2,%3}, [%4];"
        : "=r"(r[0]), "=r"(r[1]), "=r"(r[2]), "=r"(r[3]) : "r"(addr));
}
__device__ __forceinline__ void ldsm_x4_t(uint32_t r[4], uint32_t addr) {
    asm volatile("ldmatrix.sync.aligned.m8n8.x4.trans.shared.b16 {%0,%1,%2,%3}, [%4];"
        : "=r"(r[0]), "=r"(r[1]), "=r"(r[2]), "=r"(r[3]) : "r"(addr));
}

// fp16 m16n8k16 mma, fp32 accum
__device__ __forceinline__ void mma_f16(float d[4], const uint32_t a[4], const uint32_t b[2]) {
    asm volatile(
        "mma.sync.aligned.m16n8k16.row.col.f32.f16.f16.f32 "
        "{%0,%1,%2,%3}, {%4,%5,%6,%7}, {%8,%9}, {%0,%1,%2,%3};"
        : "+f"(d[0]), "+f"(d[1]), "+f"(d[2]), "+f"(d[3])
        : "r"(a[0]), "r"(a[1]), "r"(a[2]), "r"(a[3]), "r"(b[0]), "r"(b[1]));
}

__device__ __forceinline__ uint32_t packh2(float a, float b) {
    __half2 h = __floats2half2_rn(a, b);
    return *(uint32_t*)&h;
}

// ================= fp16 tensor GEMM: C[M,N] = A[M,K] @ Bt[N,K]^T =================
#define HG_STAGE_BYTES 32768
#define HG_SMEM_BYTES  (2 * HG_STAGE_BYTES)

template<bool HAS_BIAS, bool RELU, bool HAS_RES, bool OUT_HALF>
__global__ __launch_bounds__(256, 2) void hgemm(
    const __half* __restrict__ A, const __half* __restrict__ Bt,
    const float* __restrict__ bias, const float* __restrict__ res,
    void* __restrict__ Cv, int M, int N, int K, int lda, int ldb, int ldc)
{
    extern __shared__ char smem_raw[];
    const uint32_t sbase = smem_u32(smem_raw);

    const int tid = threadIdx.x, lane = tid & 31, wid = tid >> 5;
    const int wrow = (wid & 3) * 32;
    const int wcol = (wid >> 2) * 64;
    const int rowBase = blockIdx.y * 128;
    const int colBase = blockIdx.x * 128;

    auto load_chunk = [&](int c) {
        const uint32_t ast = sbase + (uint32_t)(c & 1) * HG_STAGE_BYTES;
        const uint32_t bst = ast + 16384;
        const int kOff = c * 64;
        #pragma unroll
        for (int i = 0; i < 4; i++) {
            int g = tid + i * 256;
            int r = g >> 3, cc = g & 7;
            cp_async16(ast + r * 128 + (((cc ^ (r & 7))) << 4),
                       A + (size_t)(rowBase + r) * lda + kOff + cc * 8);
        }
        #pragma unroll
        for (int i = 0; i < 4; i++) {
            int g = tid + i * 256;
            int r = g >> 3, cc = g & 7;
            cp_async16(bst + r * 128 + (((cc ^ (r & 7))) << 4),
                       Bt + (size_t)(colBase + r) * ldb + kOff + cc * 8);
        }
    };

    float acc[2][8][4];
    #pragma unroll
    for (int mt = 0; mt < 2; mt++)
        #pragma unroll
        for (int nt = 0; nt < 8; nt++)
            #pragma unroll
            for (int i = 0; i < 4; i++) acc[mt][nt][i] = 0.f;

    const int NC = K / 64;
    load_chunk(0); cp_commit();

    const int arow = wrow + (lane & 15);
    const int ahi  = lane >> 4;
    const int brow = wcol + (lane & 7) + ((lane >> 4) << 3);
    const int bhi  = (lane >> 3) & 1;

    for (int c = 0; c < NC; c++) {
        if (c + 1 < NC) load_chunk(c + 1);
        cp_commit();
        cp_wait<1>();
        __syncthreads();

        const uint32_t ast = sbase + (uint32_t)(c & 1) * HG_STAGE_BYTES;
        const uint32_t bst = ast + 16384;

        uint32_t aAddr[2], bAddr[4];
        int arx[2], brx[4];
        #pragma unroll
        for (int mt = 0; mt < 2; mt++) {
            const int r = arow + mt * 16;
            aAddr[mt] = ast + r * 128;
            arx[mt] = r & 7;
        }
        #pragma unroll
        for (int np = 0; np < 4; np++) {
            const int n = brow + np * 16;
            bAddr[np] = bst + n * 128;
            brx[np] = n & 7;
        }

        #pragma unroll
        for (int ks = 0; ks < 4; ks++) {
            uint32_t af[2][4];
            #pragma unroll
            for (int mt = 0; mt < 2; mt++)
                ldsm_x4(af[mt], aAddr[mt] + (((2 * ks + ahi) ^ arx[mt]) << 4));
            #pragma unroll
            for (int np = 0; np < 4; np++) {
                uint32_t bf[4];
                ldsm_x4(bf, bAddr[np] + (((2 * ks + bhi) ^ brx[np]) << 4));
                #pragma unroll
                for (int mt = 0; mt < 2; mt++) {
                    mma_f16(acc[mt][np * 2],     af[mt], bf);
                    mma_f16(acc[mt][np * 2 + 1], af[mt], bf + 2);
                }
            }
        }
        __syncthreads();
    }

    float* Cf = (float*)Cv;
    __half* Ch = (__half*)Cv;
    #pragma unroll
    for (int mt = 0; mt < 2; mt++) {
        const int r0 = rowBase + wrow + mt * 16 + (lane >> 2);
        #pragma unroll
        for (int nt = 0; nt < 8; nt++) {
            const int col = colBase + wcol + nt * 8 + 2 * (lane & 3);
            float vx0 = acc[mt][nt][0], vy0 = acc[mt][nt][1];
            float vx1 = acc[mt][nt][2], vy1 = acc[mt][nt][3];
            if (HAS_BIAS) {
                const float b0v = bias[col], b1v = bias[col + 1];
                vx0 += b0v; vy0 += b1v; vx1 += b0v; vy1 += b1v;
            }
            if (RELU) {
                vx0 = fmaxf(vx0, 0.f); vy0 = fmaxf(vy0, 0.f);
                vx1 = fmaxf(vx1, 0.f); vy1 = fmaxf(vy1, 0.f);
            }
            if (HAS_RES) {
                float2 rv0 = *(const float2*)(res + (size_t)r0 * ldc + col);
                float2 rv1 = *(const float2*)(res + (size_t)(r0 + 8) * ldc + col);
                vx0 += rv0.x; vy0 += rv0.y;
                vx1 += rv1.x; vy1 += rv1.y;
            }
            if (OUT_HALF) {
                *(__half2*)(Ch + (size_t)r0 * ldc + col) = __floats2half2_rn(vx0, vy0);
                *(__half2*)(Ch + (size_t)(r0 + 8) * ldc + col) = __floats2half2_rn(vx1, vy1);
            } else {
                *(float2*)(Cf + (size_t)r0 * ldc + col) = make_float2(vx0, vy0);
                *(float2*)(Cf + (size_t)(r0 + 8) * ldc + col) = make_float2(vx1, vy1);
            }
        }
    }
}

// ================= fp16 flash attention (ldmatrix + register P), fused-QKV input =================
#define OFF_K 16384
#define OFF_V (OFF_K + 2 * 8192)
#define OFF_MSK (OFF_V + 2 * 8192)
#define FA_SMEM_BYTES (OFF_MSK + 2 * 64 * 4)

__global__ __launch_bounds__(256, 1) void flash_h_kernel(
    const __half* __restrict__ qkv, const int* __restrict__ mask,
    __half* __restrict__ attn)
{
    extern __shared__ char smem_raw[];
    float* mskf = (float*)(smem_raw + OFF_MSK);
    const uint32_t sb = smem_u32(smem_raw);

    const int tid = threadIdx.x, lane = tid & 31, wid = tid >> 5;
    const int z = blockIdx.y;
    const int b = z / H_, h = z % H_;
    const int qBase = blockIdx.x * 128;
    const __half* Qg = qkv + (size_t)b * S_ * QKV_LD + h * DK_;
    const __half* Kg = Qg + D_;
    const __half* Vg = Qg + 2 * D_;

    #pragma unroll
    for (int i = 0; i < 4; i++) {
        int g = tid + i * 256;
        int r = g >> 3, cc = g & 7;
        cp_async16(sb + r * 128 + (((cc ^ (r & 7))) << 4),
                   Qg + (size_t)(qBase + r) * QKV_LD + cc * 8);
    }
    cp_commit();

    auto load_tile = [&](int c) {
        const int s = c & 1;
        const int kv0 = c * 64;
        const uint32_t kst = sb + OFF_K + s * 8192;
        const uint32_t vst = sb + OFF_V + s * 8192;
        #pragma unroll
        for (int i = 0; i < 2; i++) {
            int g = tid + i * 256;
            int r = g >> 3, cc = g & 7;
            uint32_t swz = r * 128 + (((cc ^ (r & 7))) << 4);
            cp_async16(kst + swz, Kg + (size_t)(kv0 + r) * QKV_LD + cc * 8);
            cp_async16(vst + swz, Vg + (size_t)(kv0 + r) * QKV_LD + cc * 8);
        }
        if (tid < 64)
            mskf[s * 64 + tid] = (mask[b * S_ + kv0 + tid] == 0) ? -1e30f : 0.0f;
    };

    load_tile(0);
    cp_commit();

    float m0 = -1e30f, m1 = -1e30f, l0 = 0.f, l1 = 0.f;
    float oacc[8][4];
    #pragma unroll
    for (int nt = 0; nt < 8; nt++)
        #pragma unroll
        for (int i = 0; i < 4; i++) oacc[nt][i] = 0.f;

    uint32_t qf[4][4];
    const int wrow = wid * 16;

    const int arow = wrow + (lane & 15);
    const int ahi  = lane >> 4;
    const int krow = (lane & 7) + ((lane >> 4) << 3);
    const int khi  = (lane >> 3) & 1;
    const int vg   = lane >> 3;
    const int vi   = lane & 7;

    const int NKV = S_ / 64;
    for (int c = 0; c < NKV; c++) {
        if (c + 1 < NKV) load_tile(c + 1);
        cp_commit();
        cp_wait<1>();
        __syncthreads();

        if (c == 0) {
            const int arx = arow & 7;
            #pragma unroll
            for (int ks = 0; ks < 4; ks++)
                ldsm_x4(qf[ks], sb + arow * 128 + (((2 * ks + ahi) ^ arx) << 4));
        }

        const uint32_t kst = sb + OFF_K + (c & 1) * 8192;
        const uint32_t vst = sb + OFF_V + (c & 1) * 8192;
        const float* msk = mskf + (c & 1) * 64;

        float sacc[8][4];
        #pragma unroll
        for (int nt = 0; nt < 8; nt++)
            #pragma unroll
            for (int i = 0; i < 4; i++) sacc[nt][i] = 0.f;

        #pragma unroll
        for (int ks = 0; ks < 4; ks++) {
            #pragma unroll
            for (int ng = 0; ng < 4; ng++) {
                const int row = ng * 16 + krow;
                uint32_t bf[4];
                ldsm_x4(bf, kst + row * 128 + (((2 * ks + khi) ^ (row & 7)) << 4));
                mma_f16(sacc[ng * 2],     qf[ks], bf);
                mma_f16(sacc[ng * 2 + 1], qf[ks], bf + 2);
            }
        }

        float tm0 = -1e30f, tm1 = -1e30f;
        #pragma unroll
        for (int nt = 0; nt < 8; nt++) {
            const float ma = msk[nt * 8 + 2 * (lane & 3)];
            const float mb = msk[nt * 8 + 2 * (lane & 3) + 1];
            sacc[nt][0] = sacc[nt][0] * 0.125f + ma;
            sacc[nt][1] = sacc[nt][1] * 0.125f + mb;
            sacc[nt][2] = sacc[nt][2] * 0.125f + ma;
            sacc[nt][3] = sacc[nt][3] * 0.125f + mb;
            tm0 = fmaxf(tm0, fmaxf(sacc[nt][0], sacc[nt][1]));
            tm1 = fmaxf(tm1, fmaxf(sacc[nt][2], sacc[nt][3]));
        }
        tm0 = fmaxf(tm0, __shfl_xor_sync(0xffffffffu, tm0, 1));
        tm0 = fmaxf(tm0, __shfl_xor_sync(0xffffffffu, tm0, 2));
        tm1 = fmaxf(tm1, __shfl_xor_sync(0xffffffffu, tm1, 1));
        tm1 = fmaxf(tm1, __shfl_xor_sync(0xffffffffu, tm1, 2));

        const float mn0 = fmaxf(m0, tm0), mn1 = fmaxf(m1, tm1);
        const float a0 = __expf(m0 - mn0), a1 = __expf(m1 - mn1);
        m0 = mn0; m1 = mn1;

        float rs0 = 0.f, rs1 = 0.f;
        #pragma unroll
        for (int nt = 0; nt < 8; nt++) {
            sacc[nt][0] = __expf(sacc[nt][0] - mn0);
            sacc[nt][1] = __expf(sacc[nt][1] - mn0);
            sacc[nt][2] = __expf(sacc[nt][2] - mn1);
            sacc[nt][3] = __expf(sacc[nt][3] - mn1);
            rs0 += sacc[nt][0] + sacc[nt][1];
            rs1 += sacc[nt][2] + sacc[nt][3];
        }
        rs0 += __shfl_xor_sync(0xffffffffu, rs0, 1);
        rs0 += __shfl_xor_sync(0xffffffffu, rs0, 2);
        rs1 += __shfl_xor_sync(0xffffffffu, rs1, 1);
        rs1 += __shfl_xor_sync(0xffffffffu, rs1, 2);
        l0 = l0 * a0 + rs0;
        l1 = l1 * a1 + rs1;

        uint32_t pa[4][4];
        #pragma unroll
        for (int ks = 0; ks < 4; ks++) {
            pa[ks][0] = packh2(sacc[2 * ks][0],     sacc[2 * ks][1]);
            pa[ks][1] = packh2(sacc[2 * ks][2],     sacc[2 * ks][3]);
            pa[ks][2] = packh2(sacc[2 * ks + 1][0], sacc[2 * ks + 1][1]);
            pa[ks][3] = packh2(sacc[2 * ks + 1][2], sacc[2 * ks + 1][3]);
        }

        #pragma unroll
        for (int nt = 0; nt < 8; nt++) {
            oacc[nt][0] *= a0; oacc[nt][1] *= a0;
            oacc[nt][2] *= a1; oacc[nt][3] *= a1;
        }

        #pragma unroll
        for (int ks = 0; ks < 4; ks++) {
            #pragma unroll
            for (int ng = 0; ng < 4; ng++) {
                const int row = ks * 16 + 8 * (vg & 1) + vi;
                const int cc = ng * 2 + (vg >> 1);
                uint32_t bf[4];
                ldsm_x4_t(bf, vst + row * 128 + (((cc ^ (row & 7))) << 4));
                mma_f16(oacc[ng * 2],     pa[ks], bf);
                mma_f16(oacc[ng * 2 + 1], pa[ks], bf + 2);
            }
        }
        __syncthreads();
    }

    const float inv0 = 1.0f / l0, inv1 = 1.0f / l1;
    const int r0 = qBase + wrow + (lane >> 2);
    __half* Og = attn + (size_t)b * S_ * D_ + h * DK_;
    #pragma unroll
    for (int nt = 0; nt < 8; nt++) {
        const int col = nt * 8 + 2 * (lane & 3);
        *(__half2*)(Og + (size_t)r0 * D_ + col) =
            __floats2half2_rn(oacc[nt][0] * inv0, oacc[nt][1] * inv0);
        *(__half2*)(Og + (size_t)(r0 + 8) * D_ + col) =
            __floats2half2_rn(oacc[nt][2] * inv1, oacc[nt][3] * inv1);
    }
}

// ================= weight transposes -> fp16 =================
__global__ __launch_bounds__(256) void transpose_h_kernel(
    const float* __restrict__ W, __half* __restrict__ Wt, int Kd, int Nd)
{
    __shared__ float t[32][33];
    const int k0 = blockIdx.y * 32, n0 = blockIdx.x * 32;
    const int tx = threadIdx.x & 31, ty = threadIdx.x >> 5;
    #pragma unroll
    for (int i = 0; i < 32; i += 8)
        t[ty + i][tx] = W[(size_t)(k0 + ty + i) * Nd + n0 + tx];
    __syncthreads();
    #pragma unroll
    for (int i = 0; i < 32; i += 8)
        Wt[(size_t)(n0 + ty + i) * Kd + k0 + tx] = __float2half_rn(t[tx][ty + i]);
}

// fused qkv transpose: z=0/1/2 selects wq/wk/wv -> rows [z*D, (z+1)*D) of Wt[3D, D]
__global__ __launch_bounds__(256) void transpose_qkv_kernel(
    const float* __restrict__ Wq, const float* __restrict__ Wk,
    const float* __restrict__ Wv,
    const float* __restrict__ bq, const float* __restrict__ bk,
    const float* __restrict__ bv,
    __half* __restrict__ Wt, float* __restrict__ bqkv)
{
    __shared__ float t[32][33];
    const int zz = blockIdx.z;
    const float* W = (zz == 0) ? Wq : (zz == 1) ? Wk : Wv;
    const int k0 = blockIdx.y * 32, n0 = blockIdx.x * 32;
    const int tx = threadIdx.x & 31, ty = threadIdx.x >> 5;
    #pragma unroll
    for (int i = 0; i < 32; i += 8)
        t[ty + i][tx] = W[(size_t)(k0 + ty + i) * D_ + n0 + tx];
    __syncthreads();
    #pragma unroll
    for (int i = 0; i < 32; i += 8)
        Wt[(size_t)(zz * D_ + n0 + ty + i) * D_ + k0 + tx] = __float2half_rn(t[tx][ty + i]);
    // bias concat (first block column only)
    if (blockIdx.y == 0 && threadIdx.x < 32 && blockIdx.x * 32 + threadIdx.x < D_) {
        const int n = blockIdx.x * 32 + threadIdx.x;
        const float* bb = (zz == 0) ? bq : (zz == 1) ? bk : bv;
        bqkv[zz * D_ + n] = bb[n];
    }
}

// ================= LayerNorm (ddof=1, /(std+eps)) -> fp16 output =================
__global__ __launch_bounds__(256) void ln_kernel(
    const float* __restrict__ x, const float* __restrict__ w,
    const float* __restrict__ b, __half* __restrict__ y)
{
    __shared__ float red[256];
    const int row = blockIdx.x;
    const int tid = threadIdx.x;
    const float* xr = x + (size_t)row * D_;
    float v0 = xr[tid], v1 = xr[tid + 256], v2 = xr[tid + 512], v3 = xr[tid + 768];

    red[tid] = v0 + v1 + v2 + v3; __syncthreads();
    for (int off = 128; off > 0; off >>= 1) {
        if (tid < off) red[tid] += red[tid + off];
        __syncthreads();
    }
    float mean = red[0] * (1.0f / D_);
    __syncthreads();

    float d0 = v0 - mean, d1 = v1 - mean, d2 = v2 - mean, d3 = v3 - mean;
    red[tid] = d0 * d0 + d1 * d1 + d2 * d2 + d3 * d3; __syncthreads();
    for (int off = 128; off > 0; off >>= 1) {
        if (tid < off) red[tid] += red[tid + off];
        __syncthreads();
    }
    float std1 = sqrtf(red[0] / (float)(D_ - 1));
    float rinv = 1.0f / (std1 + EPS_);

    __half* yr = y + (size_t)row * D_;
    yr[tid]       = __float2half_rn(w[tid]       * d0 * rinv + b[tid]);
    yr[tid + 256] = __float2half_rn(w[tid + 256] * d1 * rinv + b[tid + 256]);
    yr[tid + 512] = __float2half_rn(w[tid + 512] * d2 * rinv + b[tid + 512]);
    yr[tid + 768] = __float2half_rn(w[tid + 768] * d3 * rinv + b[tid + 768]);
}

// ================= host launcher =================
extern "C" void kernel_launch(void* const* d_in, const int* in_sizes, int n_in,
                              void* d_out, int out_size)
{
    const float* x    = (const float*)d_in[0];
    const int*   mask = (const int*)  d_in[1];
    const float* wq   = (const float*)d_in[2];
    const float* bq   = (const float*)d_in[3];
    const float* wk   = (const float*)d_in[4];
    const float* bk   = (const float*)d_in[5];
    const float* wv   = (const float*)d_in[6];
    const float* bv   = (const float*)d_in[7];
    const float* wo   = (const float*)d_in[8];
    const float* bo   = (const float*)d_in[9];
    const float* w1   = (const float*)d_in[10];
    const float* b1   = (const float*)d_in[11];
    const float* w2   = (const float*)d_in[12];
    const float* b2   = (const float*)d_in[13];
    const float* ln1w = (const float*)d_in[14];
    const float* ln1b = (const float*)d_in[15];
    const float* ln2w = (const float*)d_in[16];
    const float* ln2b = (const float*)d_in[17];
    float* out = (float*)d_out;

    __half *xn, *qkv, *attn, *hbuf, *wqkvT, *woT, *w1T, *w2T;
    float *x1, *bqkv;
    cudaGetSymbolAddress((void**)&xn,    g_xn_h);
    cudaGetSymbolAddress((void**)&qkv,   g_qkv_h);
    cudaGetSymbolAddress((void**)&attn,  g_attn_h);
    cudaGetSymbolAddress((void**)&x1,    g_x1);
    cudaGetSymbolAddress((void**)&hbuf,  g_h_h);
    cudaGetSymbolAddress((void**)&wqkvT, g_wqkvT);
    cudaGetSymbolAddress((void**)&bqkv,  g_bqkv);
    cudaGetSymbolAddress((void**)&woT,   g_woT);
    cudaGetSymbolAddress((void**)&w1T,   g_w1T);
    cudaGetSymbolAddress((void**)&w2T,   g_w2T);

    auto kQKV  = hgemm<true, false, false, true>;   // half out (feeds flash)
    auto kRES  = hgemm<true, false, true,  false>;  // float out + residual
    auto kFFN1 = hgemm<true, true,  false, true>;   // half out (feeds FFN2)

    cudaFuncSetAttribute(kQKV,  cudaFuncAttributeMaxDynamicSharedMemorySize, HG_SMEM_BYTES);
    cudaFuncSetAttribute(kRES,  cudaFuncAttributeMaxDynamicSharedMemorySize, HG_SMEM_BYTES);
    cudaFuncSetAttribute(kFFN1, cudaFuncAttributeMaxDynamicSharedMemorySize, HG_SMEM_BYTES);
    cudaFuncSetAttribute(flash_h_kernel, cudaFuncAttributeMaxDynamicSharedMemorySize, FA_SMEM_BYTES);

    // weight transposes (fp16): fused qkv in one launch
    {
        dim3 gQ(D_ / 32, D_ / 32, 3);
        transpose_qkv_kernel<<<gQ, 256>>>(wq, wk, wv, bq, bk, bv, wqkvT, bqkv);
        dim3 gT(D_ / 32, D_ / 32);
        transpose_h_kernel<<<gT, 256>>>(wo, woT, D_, D_);
        dim3 gT1(DFF_ / 32, D_ / 32);
        transpose_h_kernel<<<gT1, 256>>>(w1, w1T, D_, DFF_);
        dim3 gT2(D_ / 32, DFF_ / 32);
        transpose_h_kernel<<<gT2, 256>>>(w2, w2T, DFF_, D_);
    }

    // 1) LN1 -> xn (half)
    ln_kernel<<<NTOK, 256>>>(x, ln1w, ln1b, xn);

    // 2) fused QKV projection: [8192,1024] @ [1024,3072] -> half [8192,3072]
    dim3 gQKV(3 * D_ / 128, NTOK / 128);
    kQKV<<<gQKV, 256, HG_SMEM_BYTES>>>(xn, wqkvT, bqkv, nullptr, qkv,
                                       NTOK, 3 * D_, D_, D_, D_, 3 * D_);

    // 3) fp16 flash attention -> attn (half)
    dim3 gFA(S_ / 128, NBH);
    flash_h_kernel<<<gFA, 256, FA_SMEM_BYTES>>>(qkv, mask, attn);

    // 4) x1 = x + attn @ wo + bo  (float)
    dim3 gProj(D_ / 128, NTOK / 128);
    kRES<<<gProj, 256, HG_SMEM_BYTES>>>(attn, woT, bo, x, x1, NTOK, D_, D_, D_, D_, D_);

    // 5) LN2 -> xn (half)
    ln_kernel<<<NTOK, 256>>>(x1, ln2w, ln2b, xn);

    // 6) h = relu(xn @ w1 + b1) -> half
    dim3 gF1(DFF_ / 128, NTOK / 128);
    kFFN1<<<gF1, 256, HG_SMEM_BYTES>>>(xn, w1T, b1, nullptr, hbuf, NTOK, DFF_, D_, D_, D_, DFF_);

    // 7) out = x1 + h @ w2 + b2  (float)
    kRES<<<gProj, 256, HG_SMEM_BYTES>>>(hbuf, w2T, b2, x1, out, NTOK, D_, DFF_, DFF_, DFF_, D_);
}

// round 11
// speedup vs baseline: 9.1128x; 1.0109x over previous
#include <cuda_runtime.h>
#include <cuda_fp16.h>
#include <cstdint>
#include <cstddef>

#define B_ 4
#define S_ 2048
#define D_ 1024
#define H_ 16
#define DK_ 64
#define DFF_ 4096
#define EPS_ 1e-6f
#define NTOK (B_ * S_)          // 8192
#define NBH  (B_ * H_)          // 64
#define QKV_LD (3 * D_)         // fused qkv row stride

// ================= scratch (device globals; no runtime allocation) =================
__device__ __half g_xn_h[(size_t)NTOK * D_];
__device__ __half g_qkv_h[(size_t)NTOK * 3 * D_];     // fused [NTOK, 3*D] = q|k|v
__device__ __half g_attn_h[(size_t)NTOK * D_];
__device__ float  g_x1[(size_t)NTOK * D_];
__device__ __half g_h_h[(size_t)NTOK * DFF_];
// fused transposed fp16 weights
__device__ __half g_wqkvT[(size_t)3 * D_ * D_];       // [3072, 1024] K-major
__device__ float  g_bqkv[3 * D_];
__device__ __half g_woT[(size_t)D_ * D_];
__device__ __half g_w1T[(size_t)DFF_ * D_];
__device__ __half g_w2T[(size_t)D_ * DFF_];

// ================= helpers =================
__device__ __forceinline__ uint32_t smem_u32(const void* p) {
    uint32_t a;
    asm("{ .reg .u64 t; cvta.to.shared.u64 t, %1; cvt.u32.u64 %0, t; }" : "=r"(a) : "l"(p));
    return a;
}
__device__ __forceinline__ void cp_async16(uint32_t smem, const void* g) {
    asm volatile("cp.async.cg.shared.global [%0], [%1], 16;" :: "r"(smem), "l"(g));
}
__device__ __forceinline__ void cp_commit() { asm volatile("cp.async.commit_group;" ::: "memory"); }
template <int N>
__device__ __forceinline__ void cp_wait() { asm volatile("cp.async.wait_group %0;" :: "n"(N) : "memory"); }

__device__ __forceinline__ void ldsm_x4(uint32_t r[4], uint32_t addr) {
    asm volatile("ldmatrix.sync.aligned.m8n8.x4.shared.b16 {%0,%1,%2,%3}, [%4];"
        : "=r"(r[0]), "=r"(r[1]), "=r"(r[2]), "=r"(r[3]) : "r"(addr));
}
__device__ __forceinline__ void ldsm_x4_t(uint32_t r[4], uint32_t addr) {
    asm volatile("ldmatrix.sync.aligned.m8n8.x4.trans.shared.b16 {%0,%1,%2,%3}, [%4];"
        : "=r"(r[0]), "=r"(r[1]), "=r"(r[2]), "=r"(r[3]) : "r"(addr));
}

// fp16 m16n8k16 mma, fp32 accum
__device__ __forceinline__ void mma_f16(float d[4], const uint32_t a[4], const uint32_t b[2]) {
    asm volatile(
        "mma.sync.aligned.m16n8k16.row.col.f32.f16.f16.f32 "
        "{%0,%1,%2,%3}, {%4,%5,%6,%7}, {%8,%9}, {%0,%1,%2,%3};"
        : "+f"(d[0]), "+f"(d[1]), "+f"(d[2]), "+f"(d[3])
        : "r"(a[0]), "r"(a[1]), "r"(a[2]), "r"(a[3]), "r"(b[0]), "r"(b[1]));
}

__device__ __forceinline__ uint32_t packh2(float a, float b) {
    __half2 h = __floats2half2_rn(a, b);
    return *(uint32_t*)&h;
}

// ================= fp16 tensor GEMM: C[M,N] = A[M,K] @ Bt[N,K]^T =================
// 3-stage cp.async pipeline, occupancy 2.
#define HG_STAGE_BYTES 32768
#define HG_STAGES 3
#define HG_SMEM_BYTES (HG_STAGES * HG_STAGE_BYTES)

template<bool HAS_BIAS, bool RELU, bool HAS_RES, bool OUT_HALF>
__global__ __launch_bounds__(256, 2) void hgemm(
    const __half* __restrict__ A, const __half* __restrict__ Bt,
    const float* __restrict__ bias, const float* __restrict__ res,
    void* __restrict__ Cv, int M, int N, int K, int lda, int ldb, int ldc)
{
    extern __shared__ char smem_raw[];
    const uint32_t sbase = smem_u32(smem_raw);

    const int tid = threadIdx.x, lane = tid & 31, wid = tid >> 5;
    const int wrow = (wid & 3) * 32;
    const int wcol = (wid >> 2) * 64;
    const int rowBase = blockIdx.y * 128;
    const int colBase = blockIdx.x * 128;

    auto load_chunk = [&](int c) {
        const uint32_t ast = sbase + (uint32_t)(c % HG_STAGES) * HG_STAGE_BYTES;
        const uint32_t bst = ast + 16384;
        const int kOff = c * 64;
        #pragma unroll
        for (int i = 0; i < 4; i++) {
            int g = tid + i * 256;
            int r = g >> 3, cc = g & 7;
            cp_async16(ast + r * 128 + (((cc ^ (r & 7))) << 4),
                       A + (size_t)(rowBase + r) * lda + kOff + cc * 8);
        }
        #pragma unroll
        for (int i = 0; i < 4; i++) {
            int g = tid + i * 256;
            int r = g >> 3, cc = g & 7;
            cp_async16(bst + r * 128 + (((cc ^ (r & 7))) << 4),
                       Bt + (size_t)(colBase + r) * ldb + kOff + cc * 8);
        }
    };

    float acc[2][8][4];
    #pragma unroll
    for (int mt = 0; mt < 2; mt++)
        #pragma unroll
        for (int nt = 0; nt < 8; nt++)
            #pragma unroll
            for (int i = 0; i < 4; i++) acc[mt][nt][i] = 0.f;

    const int NC = K / 64;
    load_chunk(0); cp_commit();
    load_chunk(1); cp_commit();

    const int arow = wrow + (lane & 15);
    const int ahi  = lane >> 4;
    const int brow = wcol + (lane & 7) + ((lane >> 4) << 3);
    const int bhi  = (lane >> 3) & 1;

    for (int c = 0; c < NC; c++) {
        if (c + 2 < NC) load_chunk(c + 2);
        cp_commit();
        cp_wait<2>();
        __syncthreads();

        const uint32_t ast = sbase + (uint32_t)(c % HG_STAGES) * HG_STAGE_BYTES;
        const uint32_t bst = ast + 16384;

        uint32_t aAddr[2], bAddr[4];
        int arx[2], brx[4];
        #pragma unroll
        for (int mt = 0; mt < 2; mt++) {
            const int r = arow + mt * 16;
            aAddr[mt] = ast + r * 128;
            arx[mt] = r & 7;
        }
        #pragma unroll
        for (int np = 0; np < 4; np++) {
            const int n = brow + np * 16;
            bAddr[np] = bst + n * 128;
            brx[np] = n & 7;
        }

        #pragma unroll
        for (int ks = 0; ks < 4; ks++) {
            uint32_t af[2][4];
            #pragma unroll
            for (int mt = 0; mt < 2; mt++)
                ldsm_x4(af[mt], aAddr[mt] + (((2 * ks + ahi) ^ arx[mt]) << 4));
            #pragma unroll
            for (int np = 0; np < 4; np++) {
                uint32_t bf[4];
                ldsm_x4(bf, bAddr[np] + (((2 * ks + bhi) ^ brx[np]) << 4));
                #pragma unroll
                for (int mt = 0; mt < 2; mt++) {
                    mma_f16(acc[mt][np * 2],     af[mt], bf);
                    mma_f16(acc[mt][np * 2 + 1], af[mt], bf + 2);
                }
            }
        }
        __syncthreads();
    }

    float* Cf = (float*)Cv;
    __half* Ch = (__half*)Cv;
    #pragma unroll
    for (int mt = 0; mt < 2; mt++) {
        const int r0 = rowBase + wrow + mt * 16 + (lane >> 2);
        #pragma unroll
        for (int nt = 0; nt < 8; nt++) {
            const int col = colBase + wcol + nt * 8 + 2 * (lane & 3);
            float vx0 = acc[mt][nt][0], vy0 = acc[mt][nt][1];
            float vx1 = acc[mt][nt][2], vy1 = acc[mt][nt][3];
            if (HAS_BIAS) {
                const float b0v = bias[col], b1v = bias[col + 1];
                vx0 += b0v; vy0 += b1v; vx1 += b0v; vy1 += b1v;
            }
            if (RELU) {
                vx0 = fmaxf(vx0, 0.f); vy0 = fmaxf(vy0, 0.f);
                vx1 = fmaxf(vx1, 0.f); vy1 = fmaxf(vy1, 0.f);
            }
            if (HAS_RES) {
                float2 rv0 = *(const float2*)(res + (size_t)r0 * ldc + col);
                float2 rv1 = *(const float2*)(res + (size_t)(r0 + 8) * ldc + col);
                vx0 += rv0.x; vy0 += rv0.y;
                vx1 += rv1.x; vy1 += rv1.y;
            }
            if (OUT_HALF) {
                *(__half2*)(Ch + (size_t)r0 * ldc + col) = __floats2half2_rn(vx0, vy0);
                *(__half2*)(Ch + (size_t)(r0 + 8) * ldc + col) = __floats2half2_rn(vx1, vy1);
            } else {
                *(float2*)(Cf + (size_t)r0 * ldc + col) = make_float2(vx0, vy0);
                *(float2*)(Cf + (size_t)(r0 + 8) * ldc + col) = make_float2(vx1, vy1);
            }
        }
    }
}

// ================= fp16 flash attention (ldmatrix + register P), fused-QKV input =================
#define OFF_K 16384
#define OFF_V (OFF_K + 2 * 8192)
#define OFF_MSK (OFF_V + 2 * 8192)
#define FA_SMEM_BYTES (OFF_MSK + 2 * 64 * 4)

__global__ __launch_bounds__(256, 2) void flash_h_kernel(
    const __half* __restrict__ qkv, const int* __restrict__ mask,
    __half* __restrict__ attn)
{
    extern __shared__ char smem_raw[];
    float* mskf = (float*)(smem_raw + OFF_MSK);
    const uint32_t sb = smem_u32(smem_raw);

    const int tid = threadIdx.x, lane = tid & 31, wid = tid >> 5;
    const int z = blockIdx.y;
    const int b = z / H_, h = z % H_;
    const int qBase = blockIdx.x * 128;
    const __half* Qg = qkv + (size_t)b * S_ * QKV_LD + h * DK_;
    const __half* Kg = Qg + D_;
    const __half* Vg = Qg + 2 * D_;

    #pragma unroll
    for (int i = 0; i < 4; i++) {
        int g = tid + i * 256;
        int r = g >> 3, cc = g & 7;
        cp_async16(sb + r * 128 + (((cc ^ (r & 7))) << 4),
                   Qg + (size_t)(qBase + r) * QKV_LD + cc * 8);
    }
    cp_commit();

    auto load_tile = [&](int c) {
        const int s = c & 1;
        const int kv0 = c * 64;
        const uint32_t kst = sb + OFF_K + s * 8192;
        const uint32_t vst = sb + OFF_V + s * 8192;
        #pragma unroll
        for (int i = 0; i < 2; i++) {
            int g = tid + i * 256;
            int r = g >> 3, cc = g & 7;
            uint32_t swz = r * 128 + (((cc ^ (r & 7))) << 4);
            cp_async16(kst + swz, Kg + (size_t)(kv0 + r) * QKV_LD + cc * 8);
            cp_async16(vst + swz, Vg + (size_t)(kv0 + r) * QKV_LD + cc * 8);
        }
        if (tid < 64)
            mskf[s * 64 + tid] = (mask[b * S_ + kv0 + tid] == 0) ? -1e30f : 0.0f;
    };

    load_tile(0);
    cp_commit();

    float m0 = -1e30f, m1 = -1e30f, l0 = 0.f, l1 = 0.f;
    float oacc[8][4];
    #pragma unroll
    for (int nt = 0; nt < 8; nt++)
        #pragma unroll
        for (int i = 0; i < 4; i++) oacc[nt][i] = 0.f;

    uint32_t qf[4][4];
    const int wrow = wid * 16;

    const int arow = wrow + (lane & 15);
    const int ahi  = lane >> 4;
    const int krow = (lane & 7) + ((lane >> 4) << 3);
    const int khi  = (lane >> 3) & 1;
    const int vg   = lane >> 3;
    const int vi   = lane & 7;

    const int NKV = S_ / 64;
    for (int c = 0; c < NKV; c++) {
        if (c + 1 < NKV) load_tile(c + 1);
        cp_commit();
        cp_wait<1>();
        __syncthreads();

        if (c == 0) {
            const int arx = arow & 7;
            #pragma unroll
            for (int ks = 0; ks < 4; ks++)
                ldsm_x4(qf[ks], sb + arow * 128 + (((2 * ks + ahi) ^ arx) << 4));
        }

        const uint32_t kst = sb + OFF_K + (c & 1) * 8192;
        const uint32_t vst = sb + OFF_V + (c & 1) * 8192;
        const float* msk = mskf + (c & 1) * 64;

        float sacc[8][4];
        #pragma unroll
        for (int nt = 0; nt < 8; nt++)
            #pragma unroll
            for (int i = 0; i < 4; i++) sacc[nt][i] = 0.f;

        #pragma unroll
        for (int ks = 0; ks < 4; ks++) {
            #pragma unroll
            for (int ng = 0; ng < 4; ng++) {
                const int row = ng * 16 + krow;
                uint32_t bf[4];
                ldsm_x4(bf, kst + row * 128 + (((2 * ks + khi) ^ (row & 7)) << 4));
                mma_f16(sacc[ng * 2],     qf[ks], bf);
                mma_f16(sacc[ng * 2 + 1], qf[ks], bf + 2);
            }
        }

        float tm0 = -1e30f, tm1 = -1e30f;
        #pragma unroll
        for (int nt = 0; nt < 8; nt++) {
            const float ma = msk[nt * 8 + 2 * (lane & 3)];
            const float mb = msk[nt * 8 + 2 * (lane & 3) + 1];
            sacc[nt][0] = sacc[nt][0] * 0.125f + ma;
            sacc[nt][1] = sacc[nt][1] * 0.125f + mb;
            sacc[nt][2] = sacc[nt][2] * 0.125f + ma;
            sacc[nt][3] = sacc[nt][3] * 0.125f + mb;
            tm0 = fmaxf(tm0, fmaxf(sacc[nt][0], sacc[nt][1]));
            tm1 = fmaxf(tm1, fmaxf(sacc[nt][2], sacc[nt][3]));
        }
        tm0 = fmaxf(tm0, __shfl_xor_sync(0xffffffffu, tm0, 1));
        tm0 = fmaxf(tm0, __shfl_xor_sync(0xffffffffu, tm0, 2));
        tm1 = fmaxf(tm1, __shfl_xor_sync(0xffffffffu, tm1, 1));
        tm1 = fmaxf(tm1, __shfl_xor_sync(0xffffffffu, tm1, 2));

        const float mn0 = fmaxf(m0, tm0), mn1 = fmaxf(m1, tm1);
        const float a0 = __expf(m0 - mn0), a1 = __expf(m1 - mn1);
        m0 = mn0; m1 = mn1;

        float rs0 = 0.f, rs1 = 0.f;
        #pragma unroll
        for (int nt = 0; nt < 8; nt++) {
            sacc[nt][0] = __expf(sacc[nt][0] - mn0);
            sacc[nt][1] = __expf(sacc[nt][1] - mn0);
            sacc[nt][2] = __expf(sacc[nt][2] - mn1);
            sacc[nt][3] = __expf(sacc[nt][3] - mn1);
            rs0 += sacc[nt][0] + sacc[nt][1];
            rs1 += sacc[nt][2] + sacc[nt][3];
        }
        rs0 += __shfl_xor_sync(0xffffffffu, rs0, 1);
        rs0 += __shfl_xor_sync(0xffffffffu, rs0, 2);
        rs1 += __shfl_xor_sync(0xffffffffu, rs1, 1);
        rs1 += __shfl_xor_sync(0xffffffffu, rs1, 2);
        l0 = l0 * a0 + rs0;
        l1 = l1 * a1 + rs1;

        uint32_t pa[4][4];
        #pragma unroll
        for (int ks = 0; ks < 4; ks++) {
            pa[ks][0] = packh2(sacc[2 * ks][0],     sacc[2 * ks][1]);
            pa[ks][1] = packh2(sacc[2 * ks][2],     sacc[2 * ks][3]);
            pa[ks][2] = packh2(sacc[2 * ks + 1][0], sacc[2 * ks + 1][1]);
            pa[ks][3] = packh2(sacc[2 * ks + 1][2], sacc[2 * ks + 1][3]);
        }

        #pragma unroll
        for (int nt = 0; nt < 8; nt++) {
            oacc[nt][0] *= a0; oacc[nt][1] *= a0;
            oacc[nt][2] *= a1; oacc[nt][3] *= a1;
        }

        #pragma unroll
        for (int ks = 0; ks < 4; ks++) {
            #pragma unroll
            for (int ng = 0; ng < 4; ng++) {
                const int row = ks * 16 + 8 * (vg & 1) + vi;
                const int cc = ng * 2 + (vg >> 1);
                uint32_t bf[4];
                ldsm_x4_t(bf, vst + row * 128 + (((cc ^ (row & 7))) << 4));
                mma_f16(oacc[ng * 2],     pa[ks], bf);
                mma_f16(oacc[ng * 2 + 1], pa[ks], bf + 2);
            }
        }
        __syncthreads();
    }

    const float inv0 = 1.0f / l0, inv1 = 1.0f / l1;
    const int r0 = qBase + wrow + (lane >> 2);
    __half* Og = attn + (size_t)b * S_ * D_ + h * DK_;
    #pragma unroll
    for (int nt = 0; nt < 8; nt++) {
        const int col = nt * 8 + 2 * (lane & 3);
        *(__half2*)(Og + (size_t)r0 * D_ + col) =
            __floats2half2_rn(oacc[nt][0] * inv0, oacc[nt][1] * inv0);
        *(__half2*)(Og + (size_t)(r0 + 8) * D_ + col) =
            __floats2half2_rn(oacc[nt][2] * inv1, oacc[nt][3] * inv1);
    }
}

// ================= weight transposes -> fp16 =================
__global__ __launch_bounds__(256) void transpose_h_kernel(
    const float* __restrict__ W, __half* __restrict__ Wt, int Kd, int Nd)
{
    __shared__ float t[32][33];
    const int k0 = blockIdx.y * 32, n0 = blockIdx.x * 32;
    const int tx = threadIdx.x & 31, ty = threadIdx.x >> 5;
    #pragma unroll
    for (int i = 0; i < 32; i += 8)
        t[ty + i][tx] = W[(size_t)(k0 + ty + i) * Nd + n0 + tx];
    __syncthreads();
    #pragma unroll
    for (int i = 0; i < 32; i += 8)
        Wt[(size_t)(n0 + ty + i) * Kd + k0 + tx] = __float2half_rn(t[tx][ty + i]);
}

// fused qkv transpose: z selects wq/wk/wv -> rows [z*D, (z+1)*D) of Wt[3D, D]
__global__ __launch_bounds__(256) void transpose_qkv_kernel(
    const float* __restrict__ Wq, const float* __restrict__ Wk,
    const float* __restrict__ Wv,
    const float* __restrict__ bq, const float* __restrict__ bk,
    const float* __restrict__ bv,
    __half* __restrict__ Wt, float* __restrict__ bqkv)
{
    __shared__ float t[32][33];
    const int zz = blockIdx.z;
    const float* W = (zz == 0) ? Wq : (zz == 1) ? Wk : Wv;
    const int k0 = blockIdx.y * 32, n0 = blockIdx.x * 32;
    const int tx = threadIdx.x & 31, ty = threadIdx.x >> 5;
    #pragma unroll
    for (int i = 0; i < 32; i += 8)
        t[ty + i][tx] = W[(size_t)(k0 + ty + i) * D_ + n0 + tx];
    __syncthreads();
    #pragma unroll
    for (int i = 0; i < 32; i += 8)
        Wt[(size_t)(zz * D_ + n0 + ty + i) * D_ + k0 + tx] = __float2half_rn(t[tx][ty + i]);
    if (blockIdx.y == 0 && threadIdx.x < 32 && blockIdx.x * 32 + threadIdx.x < D_) {
        const int n = blockIdx.x * 32 + threadIdx.x;
        const float* bb = (zz == 0) ? bq : (zz == 1) ? bk : bv;
        bqkv[zz * D_ + n] = bb[n];
    }
}

// ================= LayerNorm (ddof=1, /(std+eps)) -> fp16 output =================
__global__ __launch_bounds__(256) void ln_kernel(
    const float* __restrict__ x, const float* __restrict__ w,
    const float* __restrict__ b, __half* __restrict__ y)
{
    __shared__ float red[256];
    const int row = blockIdx.x;
    const int tid = threadIdx.x;
    const float* xr = x + (size_t)row * D_;
    float v0 = xr[tid], v1 = xr[tid + 256], v2 = xr[tid + 512], v3 = xr[tid + 768];

    red[tid] = v0 + v1 + v2 + v3; __syncthreads();
    for (int off = 128; off > 0; off >>= 1) {
        if (tid < off) red[tid] += red[tid + off];
        __syncthreads();
    }
    float mean = red[0] * (1.0f / D_);
    __syncthreads();

    float d0 = v0 - mean, d1 = v1 - mean, d2 = v2 - mean, d3 = v3 - mean;
    red[tid] = d0 * d0 + d1 * d1 + d2 * d2 + d3 * d3; __syncthreads();
    for (int off = 128; off > 0; off >>= 1) {
        if (tid < off) red[tid] += red[tid + off];
        __syncthreads();
    }
    float std1 = sqrtf(red[0] / (float)(D_ - 1));
    float rinv = 1.0f / (std1 + EPS_);

    __half* yr = y + (size_t)row * D_;
    yr[tid]       = __float2half_rn(w[tid]       * d0 * rinv + b[tid]);
    yr[tid + 256] = __float2half_rn(w[tid + 256] * d1 * rinv + b[tid + 256]);
    yr[tid + 512] = __float2half_rn(w[tid + 512] * d2 * rinv + b[tid + 512]);
    yr[tid + 768] = __float2half_rn(w[tid + 768] * d3 * rinv + b[tid + 768]);
}

// ================= host launcher =================
extern "C" void kernel_launch(void* const* d_in, const int* in_sizes, int n_in,
                              void* d_out, int out_size)
{
    const float* x    = (const float*)d_in[0];
    const int*   mask = (const int*)  d_in[1];
    const float* wq   = (const float*)d_in[2];
    const float* bq   = (const float*)d_in[3];
    const float* wk   = (const float*)d_in[4];
    const float* bk   = (const float*)d_in[5];
    const float* wv   = (const float*)d_in[6];
    const float* bv   = (const float*)d_in[7];
    const float* wo   = (const float*)d_in[8];
    const float* bo   = (const float*)d_in[9];
    const float* w1   = (const float*)d_in[10];
    const float* b1   = (const float*)d_in[11];
    const float* w2   = (const float*)d_in[12];
    const float* b2   = (const float*)d_in[13];
    const float* ln1w = (const float*)d_in[14];
    const float* ln1b = (const float*)d_in[15];
    const float* ln2w = (const float*)d_in[16];
    const float* ln2b = (const float*)d_in[17];
    float* out = (float*)d_out;

    __half *xn, *qkv, *attn, *hbuf, *wqkvT, *woT, *w1T, *w2T;
    float *x1, *bqkv;
    cudaGetSymbolAddress((void**)&xn,    g_xn_h);
    cudaGetSymbolAddress((void**)&qkv,   g_qkv_h);
    cudaGetSymbolAddress((void**)&attn,  g_attn_h);
    cudaGetSymbolAddress((void**)&x1,    g_x1);
    cudaGetSymbolAddress((void**)&hbuf,  g_h_h);
    cudaGetSymbolAddress((void**)&wqkvT, g_wqkvT);
    cudaGetSymbolAddress((void**)&bqkv,  g_bqkv);
    cudaGetSymbolAddress((void**)&woT,   g_woT);
    cudaGetSymbolAddress((void**)&w1T,   g_w1T);
    cudaGetSymbolAddress((void**)&w2T,   g_w2T);

    auto kQKV  = hgemm<true, false, false, true>;   // half out (feeds flash)
    auto kRES  = hgemm<true, false, true,  false>;  // float out + residual
    auto kFFN1 = hgemm<true, true,  false, true>;   // half out (feeds FFN2)

    cudaFuncSetAttribute(kQKV,  cudaFuncAttributeMaxDynamicSharedMemorySize, HG_SMEM_BYTES);
    cudaFuncSetAttribute(kRES,  cudaFuncAttributeMaxDynamicSharedMemorySize, HG_SMEM_BYTES);
    cudaFuncSetAttribute(kFFN1, cudaFuncAttributeMaxDynamicSharedMemorySize, HG_SMEM_BYTES);
    cudaFuncSetAttribute(flash_h_kernel, cudaFuncAttributeMaxDynamicSharedMemorySize, FA_SMEM_BYTES);

    // weight transposes (fp16): fused qkv in one launch
    {
        dim3 gQ(D_ / 32, D_ / 32, 3);
        transpose_qkv_kernel<<<gQ, 256>>>(wq, wk, wv, bq, bk, bv, wqkvT, bqkv);
        dim3 gT(D_ / 32, D_ / 32);
        transpose_h_kernel<<<gT, 256>>>(wo, woT, D_, D_);
        dim3 gT1(DFF_ / 32, D_ / 32);
        transpose_h_kernel<<<gT1, 256>>>(w1, w1T, D_, DFF_);
        dim3 gT2(D_ / 32, DFF_ / 32);
        transpose_h_kernel<<<gT2, 256>>>(w2, w2T, DFF_, D_);
    }

    // 1) LN1 -> xn (half)
    ln_kernel<<<NTOK, 256>>>(x, ln1w, ln1b, xn);

    // 2) fused QKV projection: [8192,1024] @ [1024,3072] -> half [8192,3072]
    dim3 gQKV(3 * D_ / 128, NTOK / 128);
    kQKV<<<gQKV, 256, HG_SMEM_BYTES>>>(xn, wqkvT, bqkv, nullptr, qkv,
                                       NTOK, 3 * D_, D_, D_, D_, 3 * D_);

    // 3) fp16 flash attention -> attn (half)
    dim3 gFA(S_ / 128, NBH);
    flash_h_kernel<<<gFA, 256, FA_SMEM_BYTES>>>(qkv, mask, attn);

    // 4) x1 = x + attn @ wo + bo  (float)
    dim3 gProj(D_ / 128, NTOK / 128);
    kRES<<<gProj, 256, HG_SMEM_BYTES>>>(attn, woT, bo, x, x1, NTOK, D_, D_, D_, D_, D_);

    // 5) LN2 -> xn (half)
    ln_kernel<<<NTOK, 256>>>(x1, ln2w, ln2b, xn);

    // 6) h = relu(xn @ w1 + b1) -> half
    dim3 gF1(DFF_ / 128, NTOK / 128);
    kFFN1<<<gF1, 256, HG_SMEM_BYTES>>>(xn, w1T, b1, nullptr, hbuf, NTOK, DFF_, D_, D_, D_, DFF_);

    // 7) out = x1 + h @ w2 + b2  (float)
    kRES<<<gProj, 256, HG_SMEM_BYTES>>>(hbuf, w2T, b2, x1, out, NTOK, D_, DFF_, DFF_, DFF_, D_);
}